// round 2
// baseline (speedup 1.0000x reference)
#include <cuda_runtime.h>
#include <math.h>

#define BATCH   2
#define NQ      2048
#define NK      2048
#define DMODEL  1024
#define NH      16
#define HD      64
#define SCALE   (1.0f/32.0f)   // 1/sqrt(DIM_V) = 1/sqrt(1024)
#define EPSV    1e-8f

// Scratch (64 MB total) — __device__ globals per allocation rules.
__device__ float g_Qp[(size_t)BATCH*NQ*DMODEL];
__device__ float g_Kp[(size_t)BATCH*NK*DMODEL];
__device__ float g_Vp[(size_t)BATCH*NK*DMODEL];
__device__ float g_O [(size_t)BATCH*NQ*DMODEL];

// ---------------------------------------------------------------------------
// C[M,N] = A[M,K] * W[N,K]^T + bias[N]      (K = N = 1024, M = 4096)
// 128x128x16 tile, 256 threads, 8x8 strided micro-tile.
// ---------------------------------------------------------------------------
__global__ __launch_bounds__(256, 2)
void sgemm_bias_kernel(const float* __restrict__ A,
                       const float* __restrict__ W,
                       const float* __restrict__ bias,
                       float* __restrict__ C)
{
    const int K = DMODEL, N = DMODEL;
    __shared__ float As[128][17];
    __shared__ float Bs[128][17];

    const int tid = threadIdx.x;
    const int tx = tid & 15, ty = tid >> 4;
    const int bm = blockIdx.y * 128, bn = blockIdx.x * 128;

    float acc[8][8];
#pragma unroll
    for (int i = 0; i < 8; i++)
#pragma unroll
        for (int j = 0; j < 8; j++) acc[i][j] = 0.f;

    for (int k0 = 0; k0 < K; k0 += 16) {
#pragma unroll
        for (int it = 0; it < 2; it++) {
            int idx = tid + it * 256;
            int row = idx >> 2;
            int q4  = (idx & 3) * 4;
            float4 av = *(const float4*)(A + (size_t)(bm + row) * K + k0 + q4);
            As[row][q4+0] = av.x; As[row][q4+1] = av.y;
            As[row][q4+2] = av.z; As[row][q4+3] = av.w;
            float4 wv = *(const float4*)(W + (size_t)(bn + row) * K + k0 + q4);
            Bs[row][q4+0] = wv.x; Bs[row][q4+1] = wv.y;
            Bs[row][q4+2] = wv.z; Bs[row][q4+3] = wv.w;
        }
        __syncthreads();
#pragma unroll
        for (int k = 0; k < 16; k++) {
            float a[8], b[8];
#pragma unroll
            for (int i = 0; i < 8; i++) a[i] = As[ty + 16*i][k];
#pragma unroll
            for (int j = 0; j < 8; j++) b[j] = Bs[tx + 16*j][k];
#pragma unroll
            for (int i = 0; i < 8; i++)
#pragma unroll
                for (int j = 0; j < 8; j++)
                    acc[i][j] += a[i] * b[j];
        }
        __syncthreads();
    }

#pragma unroll
    for (int i = 0; i < 8; i++) {
        int row = bm + ty + 16*i;
#pragma unroll
        for (int j = 0; j < 8; j++) {
            int col = bn + tx + 16*j;
            C[(size_t)row * N + col] = acc[i][j] + bias[col];
        }
    }
}

// ---------------------------------------------------------------------------
// Flash-style masked attention over projected tensors.
// One CTA = 64 q-rows for one (batch, head). 256 threads, 4x4 micro-tiles.
// Reference semantics: row max taken over ALL scores (pre-mask), masked
// entries -> exp 0, denominator = sum + 1e-8.
// ---------------------------------------------------------------------------
__global__ __launch_bounds__(256, 3)
void attn_kernel(const int* __restrict__ mask)
{
    extern __shared__ float sm[];
    float (*Qs)[65] = (float(*)[65])(sm);
    float (*Ks)[65] = (float(*)[65])(sm + 64*65);
    float (*Vs)[65] = (float(*)[65])(sm + 2*64*65);
    float (*Ps)[65] = (float(*)[65])(sm + 3*64*65);

    const int tid = threadIdx.x;
    const int tx = tid & 15, ty = tid >> 4;
    const int q0 = blockIdx.x * 64;
    const int h  = blockIdx.y;
    const int b  = blockIdx.z;

    const float* Qbase = g_Qp + ((size_t)b * NQ + q0) * DMODEL + h * HD;
    const float* Kbase = g_Kp + ((size_t)b * NK) * DMODEL + h * HD;
    const float* Vbase = g_Vp + ((size_t)b * NK) * DMODEL + h * HD;
    const int*   mbase = mask + ((size_t)b * NQ + q0) * NK;

    // Load Q tile [64 x 64]
#pragma unroll
    for (int it = 0; it < 4; it++) {
        int idx = tid + it * 256;
        int row = idx >> 4;
        int q4  = (idx & 15) * 4;
        float4 v = *(const float4*)(Qbase + (size_t)row * DMODEL + q4);
        Qs[row][q4+0] = v.x; Qs[row][q4+1] = v.y;
        Qs[row][q4+2] = v.z; Qs[row][q4+3] = v.w;
    }

    float m[4], l[4], acc[4][4];
#pragma unroll
    for (int i = 0; i < 4; i++) {
        m[i] = -INFINITY; l[i] = 0.f;
#pragma unroll
        for (int j = 0; j < 4; j++) acc[i][j] = 0.f;
    }
    __syncthreads();

    for (int kt = 0; kt < NK / 64; kt++) {
        const int k0 = kt * 64;
        // Load K, V tiles [64 x 64]
#pragma unroll
        for (int it = 0; it < 4; it++) {
            int idx = tid + it * 256;
            int row = idx >> 4;
            int q4  = (idx & 15) * 4;
            float4 kv = *(const float4*)(Kbase + (size_t)(k0 + row) * DMODEL + q4);
            Ks[row][q4+0] = kv.x; Ks[row][q4+1] = kv.y;
            Ks[row][q4+2] = kv.z; Ks[row][q4+3] = kv.w;
            float4 vv = *(const float4*)(Vbase + (size_t)(k0 + row) * DMODEL + q4);
            Vs[row][q4+0] = vv.x; Vs[row][q4+1] = vv.y;
            Vs[row][q4+2] = vv.z; Vs[row][q4+3] = vv.w;
        }
        __syncthreads();

        // S = Q K^T (4x4 per thread)
        float s[4][4];
#pragma unroll
        for (int i = 0; i < 4; i++)
#pragma unroll
            for (int j = 0; j < 4; j++) s[i][j] = 0.f;
#pragma unroll 16
        for (int d = 0; d < 64; d++) {
            float q[4], kk[4];
#pragma unroll
            for (int i = 0; i < 4; i++) q[i]  = Qs[ty + 16*i][d];
#pragma unroll
            for (int j = 0; j < 4; j++) kk[j] = Ks[tx + 16*j][d];
#pragma unroll
            for (int i = 0; i < 4; i++)
#pragma unroll
                for (int j = 0; j < 4; j++)
                    s[i][j] += q[i] * kk[j];
        }

        // scale, row-max (pre-mask, matching reference), rescale running state
#pragma unroll
        for (int i = 0; i < 4; i++) {
            float mx = -INFINITY;
#pragma unroll
            for (int j = 0; j < 4; j++) {
                s[i][j] *= SCALE;
                mx = fmaxf(mx, s[i][j]);
            }
#pragma unroll
            for (int off = 1; off < 16; off <<= 1)
                mx = fmaxf(mx, __shfl_xor_sync(0xffffffffu, mx, off));
            float mn = fmaxf(m[i], mx);
            float f  = __expf(m[i] - mn);
            l[i] *= f;
#pragma unroll
            for (int j = 0; j < 4; j++) acc[i][j] *= f;
            m[i] = mn;
        }

        // P = mask ? exp(S - m) : 0; accumulate partial row sums; stash in smem
#pragma unroll
        for (int i = 0; i < 4; i++) {
            const int* mrow = mbase + (size_t)(ty + 16*i) * NK + k0;
#pragma unroll
            for (int j = 0; j < 4; j++) {
                int   mv = mrow[tx + 16*j];
                float p  = (mv != 0) ? __expf(s[i][j] - m[i]) : 0.f;
                l[i] += p;
                Ps[ty + 16*i][tx + 16*j] = p;
            }
        }
        __syncthreads();

        // acc += P * V
#pragma unroll 16
        for (int k = 0; k < 64; k++) {
            float pv[4], vv[4];
#pragma unroll
            for (int i = 0; i < 4; i++) pv[i] = Ps[ty + 16*i][k];
#pragma unroll
            for (int j = 0; j < 4; j++) vv[j] = Vs[k][tx + 16*j];
#pragma unroll
            for (int i = 0; i < 4; i++)
#pragma unroll
                for (int j = 0; j < 4; j++)
                    acc[i][j] += pv[i] * vv[j];
        }
        __syncthreads();
    }

    // finalize: reduce row sums across 16 col-threads, divide by (l + eps)
    float* Obase = g_O + ((size_t)b * NQ + q0) * DMODEL + h * HD;
#pragma unroll
    for (int i = 0; i < 4; i++) {
        float ls = l[i];
#pragma unroll
        for (int off = 1; off < 16; off <<= 1)
            ls += __shfl_xor_sync(0xffffffffu, ls, off);
        float inv = 1.f / (ls + EPSV);
#pragma unroll
        for (int j = 0; j < 4; j++)
            Obase[(size_t)(ty + 16*i) * DMODEL + tx + 16*j] = acc[i][j] * inv;
    }
}

// ---------------------------------------------------------------------------
extern "C" void kernel_launch(void* const* d_in, const int* in_sizes, int n_in,
                              void* d_out, int out_size)
{
    const float* Q    = (const float*)d_in[0];
    const float* K    = (const float*)d_in[1];
    const int*   mask = (const int*)  d_in[2];
    const float* Wq   = (const float*)d_in[3];
    const float* bq   = (const float*)d_in[4];
    const float* Wk   = (const float*)d_in[5];
    const float* bk   = (const float*)d_in[6];
    const float* Wv   = (const float*)d_in[7];
    const float* bv   = (const float*)d_in[8];
    const float* Wo   = (const float*)d_in[9];
    const float* bo   = (const float*)d_in[10];
    float* out = (float*)d_out;

    float *pQ, *pK, *pV, *pO;
    cudaGetSymbolAddress((void**)&pQ, g_Qp);
    cudaGetSymbolAddress((void**)&pK, g_Kp);
    cudaGetSymbolAddress((void**)&pV, g_Vp);
    cudaGetSymbolAddress((void**)&pO, g_O);

    const int ATTN_SMEM = 4 * 64 * 65 * sizeof(float);  // 66560 B
    cudaFuncSetAttribute(attn_kernel,
                         cudaFuncAttributeMaxDynamicSharedMemorySize, ATTN_SMEM);

    dim3 gP(DMODEL / 128, (BATCH * NQ) / 128);  // (8, 32)

    sgemm_bias_kernel<<<gP, 256>>>(Q, Wq, bq, pQ);   // Q proj
    sgemm_bias_kernel<<<gP, 256>>>(K, Wk, bk, pK);   // K proj
    sgemm_bias_kernel<<<gP, 256>>>(K, Wv, bv, pV);   // V proj

    attn_kernel<<<dim3(NQ / 64, NH, BATCH), 256, ATTN_SMEM>>>(mask);

    sgemm_bias_kernel<<<gP, 256>>>(pO, Wo, bo, out); // output proj
}

// round 7
// speedup vs baseline: 1.3263x; 1.3263x over previous
#include <cuda_runtime.h>
#include <cuda_bf16.h>
#include <math.h>
#include <stdint.h>

#define BATCH   2
#define NQ      2048
#define NK      2048
#define DMODEL  1024
#define NH      16
#define HD      64
#define SCALE   (1.0f/32.0f)   // 1/sqrt(DIM_V)
#define EPSV    1e-8f

// Scratch — __device__ globals per allocation rules.
__device__ float g_Qp[(size_t)BATCH*NQ*DMODEL];
__device__ float g_Kp[(size_t)BATCH*NK*DMODEL];
__device__ float g_Vp[(size_t)BATCH*NK*DMODEL];
__device__ float g_O [(size_t)BATCH*NQ*DMODEL];

__device__ __forceinline__ uint32_t smem_u32(const void* p) {
    return (uint32_t)__cvta_generic_to_shared(p);
}
__device__ __forceinline__ uint32_t pack_bf2(float x, float y) {
    __nv_bfloat162 h = __floats2bfloat162_rn(x, y);
    return *reinterpret_cast<uint32_t*>(&h);
}
__device__ __forceinline__ void ldsm_x4(uint32_t& r0, uint32_t& r1, uint32_t& r2,
                                        uint32_t& r3, uint32_t addr) {
    asm volatile("ldmatrix.sync.aligned.m8n8.x4.shared.b16 {%0,%1,%2,%3}, [%4];"
                 : "=r"(r0), "=r"(r1), "=r"(r2), "=r"(r3) : "r"(addr));
}
__device__ __forceinline__ void ldsm_x2(uint32_t& r0, uint32_t& r1, uint32_t addr) {
    asm volatile("ldmatrix.sync.aligned.m8n8.x2.shared.b16 {%0,%1}, [%2];"
                 : "=r"(r0), "=r"(r1) : "r"(addr));
}
#define MMA_BF16(c, a, b)                                                     \
    asm volatile("mma.sync.aligned.m16n8k16.row.col.f32.bf16.bf16.f32 "       \
                 "{%0,%1,%2,%3}, {%4,%5,%6,%7}, {%8,%9}, {%0,%1,%2,%3};"      \
                 : "+f"((c)[0]), "+f"((c)[1]), "+f"((c)[2]), "+f"((c)[3])     \
                 : "r"((a)[0]), "r"((a)[1]), "r"((a)[2]), "r"((a)[3]),        \
                   "r"((b)[0]), "r"((b)[1]))

// ---------------------------------------------------------------------------
// GEMM via mma.sync bf16 hi/lo split: C[M,N] = A[M,K] * W[N,K]^T + bias.
// M=4096, N=K=1024. CTA tile 128x128, 8 warps (warp tile 64x32), K-stage 32.
// SMEM rows padded to 40 bf16 (80 B) -> conflict-free ldmatrix phases.
// ---------------------------------------------------------------------------
#define SSTRIDE 40   // bf16 elements per smem row (32 data + 8 pad)

__global__ __launch_bounds__(256, 1)
void gemm_mma_kernel(const float* __restrict__ A, const float* __restrict__ W,
                     const float* __restrict__ bias, float* __restrict__ C)
{
    __shared__ __align__(16) __nv_bfloat16 sAhi[128 * SSTRIDE];
    __shared__ __align__(16) __nv_bfloat16 sAlo[128 * SSTRIDE];
    __shared__ __align__(16) __nv_bfloat16 sBhi[128 * SSTRIDE];
    __shared__ __align__(16) __nv_bfloat16 sBlo[128 * SSTRIDE];

    const int tid  = threadIdx.x;
    const int wid  = tid >> 5;
    const int lane = tid & 31;
    const int wm   = wid >> 2;      // 0..1  -> m offset wm*64
    const int wn   = wid & 3;       // 0..3  -> n offset wn*32
    const int bm   = blockIdx.y * 128, bn = blockIdx.x * 128;

    float c[4][4][4];
#pragma unroll
    for (int i = 0; i < 4; i++)
#pragma unroll
        for (int j = 0; j < 4; j++)
#pragma unroll
            for (int r = 0; r < 4; r++) c[i][j][r] = 0.f;

    // ldmatrix lane addressing
    const int a_row  = wm * 64 + (lane & 15);
    const int a_koff = (lane >> 4) * 16;             // bytes (8 cols * 2B)
    const uint32_t aHiB = smem_u32(sAhi) + a_row * (SSTRIDE*2) + a_koff;
    const uint32_t aLoB = smem_u32(sAlo) + a_row * (SSTRIDE*2) + a_koff;
    const int b_row  = wn * 32 + (lane & 7);
    const int b_koff = ((lane >> 3) & 1) * 16;       // bytes
    const uint32_t bHiB = smem_u32(sBhi) + b_row * (SSTRIDE*2) + b_koff;
    const uint32_t bLoB = smem_u32(sBlo) + b_row * (SSTRIDE*2) + b_koff;

    for (int s = 0; s < DMODEL / 32; s++) {
        const int k0 = s * 32;
        // Load + convert fp32 -> bf16 hi/lo. 1024 float4 per tile, 4/thread.
#pragma unroll
        for (int it = 0; it < 4; it++) {
            int f   = tid + it * 256;
            int row = f >> 3;
            int c4  = (f & 7) * 4;
            float4 v = *(const float4*)(A + (size_t)(bm + row) * DMODEL + k0 + c4);
            float hx = __bfloat162float(__float2bfloat16_rn(v.x));
            float hy = __bfloat162float(__float2bfloat16_rn(v.y));
            float hz = __bfloat162float(__float2bfloat16_rn(v.z));
            float hw = __bfloat162float(__float2bfloat16_rn(v.w));
            *(uint2*)&sAhi[row * SSTRIDE + c4] =
                make_uint2(pack_bf2(hx, hy), pack_bf2(hz, hw));
            *(uint2*)&sAlo[row * SSTRIDE + c4] =
                make_uint2(pack_bf2(v.x - hx, v.y - hy), pack_bf2(v.z - hz, v.w - hw));
        }
#pragma unroll
        for (int it = 0; it < 4; it++) {
            int f   = tid + it * 256;
            int row = f >> 3;
            int c4  = (f & 7) * 4;
            float4 v = *(const float4*)(W + (size_t)(bn + row) * DMODEL + k0 + c4);
            float hx = __bfloat162float(__float2bfloat16_rn(v.x));
            float hy = __bfloat162float(__float2bfloat16_rn(v.y));
            float hz = __bfloat162float(__float2bfloat16_rn(v.z));
            float hw = __bfloat162float(__float2bfloat16_rn(v.w));
            *(uint2*)&sBhi[row * SSTRIDE + c4] =
                make_uint2(pack_bf2(hx, hy), pack_bf2(hz, hw));
            *(uint2*)&sBlo[row * SSTRIDE + c4] =
                make_uint2(pack_bf2(v.x - hx, v.y - hy), pack_bf2(v.z - hz, v.w - hw));
        }
        __syncthreads();

#pragma unroll
        for (int ks = 0; ks < 32; ks += 16) {
            uint32_t ah[4][4], al[4][4], bh[4][2], bl[4][2];
#pragma unroll
            for (int i = 0; i < 4; i++) {
                uint32_t off = (uint32_t)(i * 16 * (SSTRIDE*2) + ks * 2);
                ldsm_x4(ah[i][0], ah[i][1], ah[i][2], ah[i][3], aHiB + off);
                ldsm_x4(al[i][0], al[i][1], al[i][2], al[i][3], aLoB + off);
            }
#pragma unroll
            for (int j = 0; j < 4; j++) {
                uint32_t off = (uint32_t)(j * 8 * (SSTRIDE*2) + ks * 2);
                ldsm_x2(bh[j][0], bh[j][1], bHiB + off);
                ldsm_x2(bl[j][0], bl[j][1], bLoB + off);
            }
#pragma unroll
            for (int i = 0; i < 4; i++)
#pragma unroll
                for (int j = 0; j < 4; j++) {
                    MMA_BF16(c[i][j], ah[i], bh[j]);
                    MMA_BF16(c[i][j], ah[i], bl[j]);
                    MMA_BF16(c[i][j], al[i], bh[j]);
                }
        }
        __syncthreads();
    }

    // Epilogue: bias + store (float2 per fragment row)
#pragma unroll
    for (int j = 0; j < 4; j++) {
        int col = bn + wn * 32 + j * 8 + (lane & 3) * 2;
        float bx = bias[col], by = bias[col + 1];
#pragma unroll
        for (int i = 0; i < 4; i++) {
            int row0 = bm + wm * 64 + i * 16 + (lane >> 2);
            float2 v0 = make_float2(c[i][j][0] + bx, c[i][j][1] + by);
            float2 v1 = make_float2(c[i][j][2] + bx, c[i][j][3] + by);
            *(float2*)(C + (size_t)row0 * DMODEL + col)       = v0;
            *(float2*)(C + (size_t)(row0 + 8) * DMODEL + col) = v1;
        }
    }
}

// ---------------------------------------------------------------------------
// Flash-style masked attention (fp32 SIMT, unchanged from Round 2).
// ---------------------------------------------------------------------------
__global__ __launch_bounds__(256, 3)
void attn_kernel(const int* __restrict__ mask)
{
    extern __shared__ float sm[];
    float (*Qs)[65] = (float(*)[65])(sm);
    float (*Ks)[65] = (float(*)[65])(sm + 64*65);
    float (*Vs)[65] = (float(*)[65])(sm + 2*64*65);
    float (*Ps)[65] = (float(*)[65])(sm + 3*64*65);

    const int tid = threadIdx.x;
    const int tx = tid & 15, ty = tid >> 4;
    const int q0 = blockIdx.x * 64;
    const int h  = blockIdx.y;
    const int b  = blockIdx.z;

    const float* Qbase = g_Qp + ((size_t)b * NQ + q0) * DMODEL + h * HD;
    const float* Kbase = g_Kp + ((size_t)b * NK) * DMODEL + h * HD;
    const float* Vbase = g_Vp + ((size_t)b * NK) * DMODEL + h * HD;
    const int*   mbase = mask + ((size_t)b * NQ + q0) * NK;

#pragma unroll
    for (int it = 0; it < 4; it++) {
        int idx = tid + it * 256;
        int row = idx >> 4;
        int q4  = (idx & 15) * 4;
        float4 v = *(const float4*)(Qbase + (size_t)row * DMODEL + q4);
        Qs[row][q4+0] = v.x; Qs[row][q4+1] = v.y;
        Qs[row][q4+2] = v.z; Qs[row][q4+3] = v.w;
    }

    float m[4], l[4], acc[4][4];
#pragma unroll
    for (int i = 0; i < 4; i++) {
        m[i] = -INFINITY; l[i] = 0.f;
#pragma unroll
        for (int j = 0; j < 4; j++) acc[i][j] = 0.f;
    }
    __syncthreads();

    for (int kt = 0; kt < NK / 64; kt++) {
        const int k0 = kt * 64;
#pragma unroll
        for (int it = 0; it < 4; it++) {
            int idx = tid + it * 256;
            int row = idx >> 4;
            int q4  = (idx & 15) * 4;
            float4 kv = *(const float4*)(Kbase + (size_t)(k0 + row) * DMODEL + q4);
            Ks[row][q4+0] = kv.x; Ks[row][q4+1] = kv.y;
            Ks[row][q4+2] = kv.z; Ks[row][q4+3] = kv.w;
            float4 vv = *(const float4*)(Vbase + (size_t)(k0 + row) * DMODEL + q4);
            Vs[row][q4+0] = vv.x; Vs[row][q4+1] = vv.y;
            Vs[row][q4+2] = vv.z; Vs[row][q4+3] = vv.w;
        }
        __syncthreads();

        float s[4][4];
#pragma unroll
        for (int i = 0; i < 4; i++)
#pragma unroll
            for (int j = 0; j < 4; j++) s[i][j] = 0.f;
#pragma unroll 16
        for (int d = 0; d < 64; d++) {
            float q[4], kk[4];
#pragma unroll
            for (int i = 0; i < 4; i++) q[i]  = Qs[ty + 16*i][d];
#pragma unroll
            for (int j = 0; j < 4; j++) kk[j] = Ks[tx + 16*j][d];
#pragma unroll
            for (int i = 0; i < 4; i++)
#pragma unroll
                for (int j = 0; j < 4; j++)
                    s[i][j] += q[i] * kk[j];
        }

#pragma unroll
        for (int i = 0; i < 4; i++) {
            float mx = -INFINITY;
#pragma unroll
            for (int j = 0; j < 4; j++) {
                s[i][j] *= SCALE;
                mx = fmaxf(mx, s[i][j]);
            }
#pragma unroll
            for (int off = 1; off < 16; off <<= 1)
                mx = fmaxf(mx, __shfl_xor_sync(0xffffffffu, mx, off));
            float mn = fmaxf(m[i], mx);
            float f  = __expf(m[i] - mn);
            l[i] *= f;
#pragma unroll
            for (int j = 0; j < 4; j++) acc[i][j] *= f;
            m[i] = mn;
        }

#pragma unroll
        for (int i = 0; i < 4; i++) {
            const int* mrow = mbase + (size_t)(ty + 16*i) * NK + k0;
#pragma unroll
            for (int j = 0; j < 4; j++) {
                int   mv = mrow[tx + 16*j];
                float p  = (mv != 0) ? __expf(s[i][j] - m[i]) : 0.f;
                l[i] += p;
                Ps[ty + 16*i][tx + 16*j] = p;
            }
        }
        __syncthreads();

#pragma unroll 16
        for (int k = 0; k < 64; k++) {
            float pv[4], vv[4];
#pragma unroll
            for (int i = 0; i < 4; i++) pv[i] = Ps[ty + 16*i][k];
#pragma unroll
            for (int j = 0; j < 4; j++) vv[j] = Vs[k][tx + 16*j];
#pragma unroll
            for (int i = 0; i < 4; i++)
#pragma unroll
                for (int j = 0; j < 4; j++)
                    acc[i][j] += pv[i] * vv[j];
        }
        __syncthreads();
    }

    float* Obase = g_O + ((size_t)b * NQ + q0) * DMODEL + h * HD;
#pragma unroll
    for (int i = 0; i < 4; i++) {
        float ls = l[i];
#pragma unroll
        for (int off = 1; off < 16; off <<= 1)
            ls += __shfl_xor_sync(0xffffffffu, ls, off);
        float inv = 1.f / (ls + EPSV);
#pragma unroll
        for (int j = 0; j < 4; j++)
            Obase[(size_t)(ty + 16*i) * DMODEL + tx + 16*j] = acc[i][j] * inv;
    }
}

// ---------------------------------------------------------------------------
extern "C" void kernel_launch(void* const* d_in, const int* in_sizes, int n_in,
                              void* d_out, int out_size)
{
    const float* Q    = (const float*)d_in[0];
    const float* K    = (const float*)d_in[1];
    const int*   mask = (const int*)  d_in[2];
    const float* Wq   = (const float*)d_in[3];
    const float* bq   = (const float*)d_in[4];
    const float* Wk   = (const float*)d_in[5];
    const float* bk   = (const float*)d_in[6];
    const float* Wv   = (const float*)d_in[7];
    const float* bv   = (const float*)d_in[8];
    const float* Wo   = (const float*)d_in[9];
    const float* bo   = (const float*)d_in[10];
    float* out = (float*)d_out;

    float *pQ, *pK, *pV, *pO;
    cudaGetSymbolAddress((void**)&pQ, g_Qp);
    cudaGetSymbolAddress((void**)&pK, g_Kp);
    cudaGetSymbolAddress((void**)&pV, g_Vp);
    cudaGetSymbolAddress((void**)&pO, g_O);

    const int ATTN_SMEM = 4 * 64 * 65 * sizeof(float);  // 66560 B
    cudaFuncSetAttribute(attn_kernel,
                         cudaFuncAttributeMaxDynamicSharedMemorySize, ATTN_SMEM);

    dim3 gG(DMODEL / 128, (BATCH * NQ) / 128);  // (8, 32)

    gemm_mma_kernel<<<gG, 256>>>(Q, Wq, bq, pQ);
    gemm_mma_kernel<<<gG, 256>>>(K, Wk, bk, pK);
    gemm_mma_kernel<<<gG, 256>>>(K, Wv, bv, pV);

    attn_kernel<<<dim3(NQ / 64, NH, BATCH), 256, ATTN_SMEM>>>(mask);

    gemm_mma_kernel<<<gG, 256>>>(pO, Wo, bo, out);
}

// round 8
// speedup vs baseline: 2.3814x; 1.7955x over previous
#include <cuda_runtime.h>
#include <cuda_bf16.h>
#include <math.h>
#include <stdint.h>

#define BATCH   2
#define NQ      2048
#define NK      2048
#define DMODEL  1024
#define NH      16
#define HD      64
#define SCALE   (1.0f/32.0f)   // 1/sqrt(DIM_V)
#define EPSV    1e-8f

// Scratch — __device__ globals per allocation rules.
__device__ float g_Qp[(size_t)BATCH*NQ*DMODEL];
__device__ float g_Kp[(size_t)BATCH*NK*DMODEL];
__device__ float g_Vp[(size_t)BATCH*NK*DMODEL];
__device__ float g_O [(size_t)BATCH*NQ*DMODEL];

__device__ __forceinline__ uint32_t smem_u32(const void* p) {
    return (uint32_t)__cvta_generic_to_shared(p);
}
__device__ __forceinline__ uint32_t pack_bf2(float x, float y) {
    __nv_bfloat162 h = __floats2bfloat162_rn(x, y);
    return *reinterpret_cast<uint32_t*>(&h);
}
__device__ __forceinline__ void ldsm_x4(uint32_t& r0, uint32_t& r1, uint32_t& r2,
                                        uint32_t& r3, uint32_t addr) {
    asm volatile("ldmatrix.sync.aligned.m8n8.x4.shared.b16 {%0,%1,%2,%3}, [%4];"
                 : "=r"(r0), "=r"(r1), "=r"(r2), "=r"(r3) : "r"(addr));
}
__device__ __forceinline__ void ldsm_x2(uint32_t& r0, uint32_t& r1, uint32_t addr) {
    asm volatile("ldmatrix.sync.aligned.m8n8.x2.shared.b16 {%0,%1}, [%2];"
                 : "=r"(r0), "=r"(r1) : "r"(addr));
}
__device__ __forceinline__ void ldsm_x4_t(uint32_t& r0, uint32_t& r1, uint32_t& r2,
                                          uint32_t& r3, uint32_t addr) {
    asm volatile("ldmatrix.sync.aligned.m8n8.x4.trans.shared.b16 {%0,%1,%2,%3}, [%4];"
                 : "=r"(r0), "=r"(r1), "=r"(r2), "=r"(r3) : "r"(addr));
}
#define MMA_BF16(c, a, b)                                                     \
    asm volatile("mma.sync.aligned.m16n8k16.row.col.f32.bf16.bf16.f32 "       \
                 "{%0,%1,%2,%3}, {%4,%5,%6,%7}, {%8,%9}, {%0,%1,%2,%3};"      \
                 : "+f"((c)[0]), "+f"((c)[1]), "+f"((c)[2]), "+f"((c)[3])     \
                 : "r"((a)[0]), "r"((a)[1]), "r"((a)[2]), "r"((a)[3]),        \
                   "r"((b)[0]), "r"((b)[1]))

// ---------------------------------------------------------------------------
// GEMM via mma.sync bf16 hi/lo split: C[M,N] = A[M,K] * W[N,K]^T + bias.
// (unchanged from R7 — validated at rel_err 5e-6)
// ---------------------------------------------------------------------------
#define SSTRIDE 40

__global__ __launch_bounds__(256, 1)
void gemm_mma_kernel(const float* __restrict__ A, const float* __restrict__ W,
                     const float* __restrict__ bias, float* __restrict__ C)
{
    __shared__ __align__(16) __nv_bfloat16 sAhi[128 * SSTRIDE];
    __shared__ __align__(16) __nv_bfloat16 sAlo[128 * SSTRIDE];
    __shared__ __align__(16) __nv_bfloat16 sBhi[128 * SSTRIDE];
    __shared__ __align__(16) __nv_bfloat16 sBlo[128 * SSTRIDE];

    const int tid  = threadIdx.x;
    const int wid  = tid >> 5;
    const int lane = tid & 31;
    const int wm   = wid >> 2;
    const int wn   = wid & 3;
    const int bm   = blockIdx.y * 128, bn = blockIdx.x * 128;

    float c[4][4][4];
#pragma unroll
    for (int i = 0; i < 4; i++)
#pragma unroll
        for (int j = 0; j < 4; j++)
#pragma unroll
            for (int r = 0; r < 4; r++) c[i][j][r] = 0.f;

    const int a_row  = wm * 64 + (lane & 15);
    const int a_koff = (lane >> 4) * 16;
    const uint32_t aHiB = smem_u32(sAhi) + a_row * (SSTRIDE*2) + a_koff;
    const uint32_t aLoB = smem_u32(sAlo) + a_row * (SSTRIDE*2) + a_koff;
    const int b_row  = wn * 32 + (lane & 7);
    const int b_koff = ((lane >> 3) & 1) * 16;
    const uint32_t bHiB = smem_u32(sBhi) + b_row * (SSTRIDE*2) + b_koff;
    const uint32_t bLoB = smem_u32(sBlo) + b_row * (SSTRIDE*2) + b_koff;

    for (int s = 0; s < DMODEL / 32; s++) {
        const int k0 = s * 32;
#pragma unroll
        for (int it = 0; it < 4; it++) {
            int f   = tid + it * 256;
            int row = f >> 3;
            int c4  = (f & 7) * 4;
            float4 v = *(const float4*)(A + (size_t)(bm + row) * DMODEL + k0 + c4);
            float hx = __bfloat162float(__float2bfloat16_rn(v.x));
            float hy = __bfloat162float(__float2bfloat16_rn(v.y));
            float hz = __bfloat162float(__float2bfloat16_rn(v.z));
            float hw = __bfloat162float(__float2bfloat16_rn(v.w));
            *(uint2*)&sAhi[row * SSTRIDE + c4] =
                make_uint2(pack_bf2(hx, hy), pack_bf2(hz, hw));
            *(uint2*)&sAlo[row * SSTRIDE + c4] =
                make_uint2(pack_bf2(v.x - hx, v.y - hy), pack_bf2(v.z - hz, v.w - hw));
        }
#pragma unroll
        for (int it = 0; it < 4; it++) {
            int f   = tid + it * 256;
            int row = f >> 3;
            int c4  = (f & 7) * 4;
            float4 v = *(const float4*)(W + (size_t)(bn + row) * DMODEL + k0 + c4);
            float hx = __bfloat162float(__float2bfloat16_rn(v.x));
            float hy = __bfloat162float(__float2bfloat16_rn(v.y));
            float hz = __bfloat162float(__float2bfloat16_rn(v.z));
            float hw = __bfloat162float(__float2bfloat16_rn(v.w));
            *(uint2*)&sBhi[row * SSTRIDE + c4] =
                make_uint2(pack_bf2(hx, hy), pack_bf2(hz, hw));
            *(uint2*)&sBlo[row * SSTRIDE + c4] =
                make_uint2(pack_bf2(v.x - hx, v.y - hy), pack_bf2(v.z - hz, v.w - hw));
        }
        __syncthreads();

#pragma unroll
        for (int ks = 0; ks < 32; ks += 16) {
            uint32_t ah[4][4], al[4][4], bh[4][2], bl[4][2];
#pragma unroll
            for (int i = 0; i < 4; i++) {
                uint32_t off = (uint32_t)(i * 16 * (SSTRIDE*2) + ks * 2);
                ldsm_x4(ah[i][0], ah[i][1], ah[i][2], ah[i][3], aHiB + off);
                ldsm_x4(al[i][0], al[i][1], al[i][2], al[i][3], aLoB + off);
            }
#pragma unroll
            for (int j = 0; j < 4; j++) {
                uint32_t off = (uint32_t)(j * 8 * (SSTRIDE*2) + ks * 2);
                ldsm_x2(bh[j][0], bh[j][1], bHiB + off);
                ldsm_x2(bl[j][0], bl[j][1], bLoB + off);
            }
#pragma unroll
            for (int i = 0; i < 4; i++)
#pragma unroll
                for (int j = 0; j < 4; j++) {
                    MMA_BF16(c[i][j], ah[i], bh[j]);
                    MMA_BF16(c[i][j], ah[i], bl[j]);
                    MMA_BF16(c[i][j], al[i], bh[j]);
                }
        }
        __syncthreads();
    }

#pragma unroll
    for (int j = 0; j < 4; j++) {
        int col = bn + wn * 32 + j * 8 + (lane & 3) * 2;
        float bx = bias[col], by = bias[col + 1];
#pragma unroll
        for (int i = 0; i < 4; i++) {
            int row0 = bm + wm * 64 + i * 16 + (lane >> 2);
            float2 v0 = make_float2(c[i][j][0] + bx, c[i][j][1] + by);
            float2 v1 = make_float2(c[i][j][2] + bx, c[i][j][3] + by);
            *(float2*)(C + (size_t)row0 * DMODEL + col)       = v0;
            *(float2*)(C + (size_t)(row0 + 8) * DMODEL + col) = v1;
        }
    }
}

// ---------------------------------------------------------------------------
// Flash attention via mma.sync. CTA = 128 q-rows x one (b,h). 8 warps, each
// 16 q-rows. k-tile = 64. S = QK^T single bf16 (scale folded into Q);
// P*V with bf16 hi/lo split (3 MMAs). P stays in registers (C-frag == A-frag).
// Reference semantics: row max over ALL (pre-mask) scores; masked -> 0;
// denominator sum + 1e-8.
// ---------------------------------------------------------------------------
#define ASTR 72   // bf16 elems per smem row (64 data + 8 pad) = 144 B

__global__ __launch_bounds__(256)
void attn_mma_kernel(const int* __restrict__ mask)
{
    __shared__ __align__(16) char sraw[3 * 64 * ASTR * 2];   // 27648 B
    __nv_bfloat16* sQ   = (__nv_bfloat16*)sraw;              // 128*72*2 = 18432 (staging, pre-loop)
    __nv_bfloat16* sK   = (__nv_bfloat16*)sraw;              // 64*72
    __nv_bfloat16* sVhi = (__nv_bfloat16*)(sraw + 64*ASTR*2);
    __nv_bfloat16* sVlo = (__nv_bfloat16*)(sraw + 2*64*ASTR*2);

    const int tid = threadIdx.x;
    const int w   = tid >> 5;
    const int L   = tid & 31;
    const int qr  = L >> 2;          // 0..7
    const int qc  = L & 3;           // 0..3
    const int q0  = blockIdx.x * 128;
    const int h   = blockIdx.y;
    const int b   = blockIdx.z;

    // ---- Stage Q tile [128 x 64], scaled by 1/32, bf16-rounded ----
    {
        const float* Qb = g_Qp + ((size_t)b * NQ + q0) * DMODEL + h * HD;
#pragma unroll
        for (int it = 0; it < 8; it++) {
            int f   = tid + it * 256;
            int row = f >> 4;
            int c4  = (f & 15) * 4;
            float4 v = *(const float4*)(Qb + (size_t)row * DMODEL + c4);
            *(uint2*)&sQ[row * ASTR + c4] =
                make_uint2(pack_bf2(v.x * SCALE, v.y * SCALE),
                           pack_bf2(v.z * SCALE, v.w * SCALE));
        }
    }
    __syncthreads();

    // Q A-fragments: 4 k-steps x 4 regs
    uint32_t qa[4][4];
    {
        uint32_t base = smem_u32(sQ) + (w * 16 + (L & 15)) * (ASTR*2) + (L >> 4) * 16;
#pragma unroll
        for (int kk = 0; kk < 4; kk++)
            ldsm_x4(qa[kk][0], qa[kk][1], qa[kk][2], qa[kk][3], base + kk * 32);
    }
    __syncthreads();   // done reading sQ; smem now reusable for K/V

    float m0 = -INFINITY, m1 = -INFINITY, l0 = 0.f, l1 = 0.f;
    float o[8][4];
#pragma unroll
    for (int j = 0; j < 8; j++)
#pragma unroll
        for (int r = 0; r < 4; r++) o[j][r] = 0.f;

    const int* mrow0 = mask + ((size_t)(b * NQ + q0 + w * 16 + qr)) * NK + 2 * qc;
    const int* mrow1 = mrow0 + (size_t)8 * NK;

    const uint32_t kB  = smem_u32(sK)   + (L & 7) * (ASTR*2) + (L >> 3) * 16;
    const uint32_t vHB = smem_u32(sVhi) + L * (ASTR*2);
    const uint32_t vLB = smem_u32(sVlo) + L * (ASTR*2);

    for (int kt = 0; kt < NK / 64; kt++) {
        const int k0 = kt * 64;
        // ---- load K (bf16) and V (bf16 hi/lo) tiles [64 x 64] ----
        {
            const float* Kb = g_Kp + ((size_t)b * NK + k0) * DMODEL + h * HD;
            const float* Vb = g_Vp + ((size_t)b * NK + k0) * DMODEL + h * HD;
#pragma unroll
            for (int it = 0; it < 4; it++) {
                int f   = tid + it * 256;
                int row = f >> 4;
                int c4  = (f & 15) * 4;
                float4 kv = *(const float4*)(Kb + (size_t)row * DMODEL + c4);
                *(uint2*)&sK[row * ASTR + c4] =
                    make_uint2(pack_bf2(kv.x, kv.y), pack_bf2(kv.z, kv.w));
                float4 vv = *(const float4*)(Vb + (size_t)row * DMODEL + c4);
                float hx = __bfloat162float(__float2bfloat16_rn(vv.x));
                float hy = __bfloat162float(__float2bfloat16_rn(vv.y));
                float hz = __bfloat162float(__float2bfloat16_rn(vv.z));
                float hw = __bfloat162float(__float2bfloat16_rn(vv.w));
                *(uint2*)&sVhi[row * ASTR + c4] =
                    make_uint2(pack_bf2(hx, hy), pack_bf2(hz, hw));
                *(uint2*)&sVlo[row * ASTR + c4] =
                    make_uint2(pack_bf2(vv.x - hx, vv.y - hy),
                               pack_bf2(vv.z - hz, vv.w - hw));
            }
        }
        __syncthreads();

        // ---- S = Q K^T : 8 n-tiles (64 k-cols), 4 k-steps each ----
        float c[8][4];
#pragma unroll
        for (int j = 0; j < 8; j++) {
            uint32_t kb0[4], kb1[4];
            uint32_t a0 = kB + j * 8 * (ASTR*2);
            ldsm_x4(kb0[0], kb0[1], kb0[2], kb0[3], a0);        // d 0..31
            ldsm_x4(kb1[0], kb1[1], kb1[2], kb1[3], a0 + 64);   // d 32..63
            c[j][0] = c[j][1] = c[j][2] = c[j][3] = 0.f;
            MMA_BF16(c[j], qa[0], &kb0[0]);
            MMA_BF16(c[j], qa[1], &kb0[2]);
            MMA_BF16(c[j], qa[2], &kb1[0]);
            MMA_BF16(c[j], qa[3], &kb1[2]);
        }

        // ---- online softmax: pre-mask row max ----
        float mx0 = -INFINITY, mx1 = -INFINITY;
#pragma unroll
        for (int j = 0; j < 8; j++) {
            mx0 = fmaxf(mx0, fmaxf(c[j][0], c[j][1]));
            mx1 = fmaxf(mx1, fmaxf(c[j][2], c[j][3]));
        }
        mx0 = fmaxf(mx0, __shfl_xor_sync(0xffffffffu, mx0, 1));
        mx0 = fmaxf(mx0, __shfl_xor_sync(0xffffffffu, mx0, 2));
        mx1 = fmaxf(mx1, __shfl_xor_sync(0xffffffffu, mx1, 1));
        mx1 = fmaxf(mx1, __shfl_xor_sync(0xffffffffu, mx1, 2));
        float nm0 = fmaxf(m0, mx0), nm1 = fmaxf(m1, mx1);
        float f0 = __expf(m0 - nm0), f1 = __expf(m1 - nm1);
        l0 *= f0; l1 *= f1;
#pragma unroll
        for (int j = 0; j < 8; j++) {
            o[j][0] *= f0; o[j][1] *= f0; o[j][2] *= f1; o[j][3] *= f1;
        }
        m0 = nm0; m1 = nm1;

        // ---- P = mask ? exp(S - m) : 0 ; pack hi/lo A-fragments ----
        uint32_t ph[4][4], pl[4][4];
#pragma unroll
        for (int kk = 0; kk < 4; kk++) {
#pragma unroll
            for (int hh = 0; hh < 2; hh++) {
                int j = kk * 2 + hh;
                int2 mv0 = *(const int2*)(mrow0 + k0 + 8 * j);
                int2 mv1 = *(const int2*)(mrow1 + k0 + 8 * j);
                float p0 = mv0.x ? __expf(c[j][0] - m0) : 0.f;
                float p1 = mv0.y ? __expf(c[j][1] - m0) : 0.f;
                float p2 = mv1.x ? __expf(c[j][2] - m1) : 0.f;
                float p3 = mv1.y ? __expf(c[j][3] - m1) : 0.f;
                l0 += p0 + p1; l1 += p2 + p3;
                float h0 = __bfloat162float(__float2bfloat16_rn(p0));
                float h1 = __bfloat162float(__float2bfloat16_rn(p1));
                float h2 = __bfloat162float(__float2bfloat16_rn(p2));
                float h3 = __bfloat162float(__float2bfloat16_rn(p3));
                ph[kk][2*hh]   = pack_bf2(p0, p1);
                ph[kk][2*hh+1] = pack_bf2(p2, p3);
                pl[kk][2*hh]   = pack_bf2(p0 - h0, p1 - h1);
                pl[kk][2*hh+1] = pack_bf2(p2 - h2, p3 - h3);
            }
        }

        // ---- O += P * V (V^T fragments via ldmatrix.trans), hi/lo split ----
#pragma unroll
        for (int j = 0; j < 8; j++) {
            uint32_t vh0[4], vh1[4], vl0[4], vl1[4];
            ldsm_x4_t(vh0[0], vh0[1], vh0[2], vh0[3], vHB + j * 16);                    // k 0..31
            ldsm_x4_t(vh1[0], vh1[1], vh1[2], vh1[3], vHB + 32 * (ASTR*2) + j * 16);    // k 32..63
            ldsm_x4_t(vl0[0], vl0[1], vl0[2], vl0[3], vLB + j * 16);
            ldsm_x4_t(vl1[0], vl1[1], vl1[2], vl1[3], vLB + 32 * (ASTR*2) + j * 16);
            MMA_BF16(o[j], ph[0], &vh0[0]);
            MMA_BF16(o[j], ph[1], &vh0[2]);
            MMA_BF16(o[j], ph[2], &vh1[0]);
            MMA_BF16(o[j], ph[3], &vh1[2]);
            MMA_BF16(o[j], ph[0], &vl0[0]);
            MMA_BF16(o[j], ph[1], &vl0[2]);
            MMA_BF16(o[j], ph[2], &vl1[0]);
            MMA_BF16(o[j], ph[3], &vl1[2]);
            MMA_BF16(o[j], pl[0], &vh0[0]);
            MMA_BF16(o[j], pl[1], &vh0[2]);
            MMA_BF16(o[j], pl[2], &vh1[0]);
            MMA_BF16(o[j], pl[3], &vh1[2]);
        }
        __syncthreads();   // all warps done with smem before next-tile overwrite
    }

    // ---- finalize: reduce l across quad, divide, store ----
    l0 += __shfl_xor_sync(0xffffffffu, l0, 1);
    l0 += __shfl_xor_sync(0xffffffffu, l0, 2);
    l1 += __shfl_xor_sync(0xffffffffu, l1, 1);
    l1 += __shfl_xor_sync(0xffffffffu, l1, 2);
    float inv0 = 1.f / (l0 + EPSV);
    float inv1 = 1.f / (l1 + EPSV);

    float* Ob = g_O + ((size_t)b * NQ + q0 + w * 16) * DMODEL + h * HD;
#pragma unroll
    for (int j = 0; j < 8; j++) {
        int col = 8 * j + 2 * qc;
        *(float2*)(Ob + (size_t)qr * DMODEL + col) =
            make_float2(o[j][0] * inv0, o[j][1] * inv0);
        *(float2*)(Ob + (size_t)(qr + 8) * DMODEL + col) =
            make_float2(o[j][2] * inv1, o[j][3] * inv1);
    }
}

// ---------------------------------------------------------------------------
extern "C" void kernel_launch(void* const* d_in, const int* in_sizes, int n_in,
                              void* d_out, int out_size)
{
    const float* Q    = (const float*)d_in[0];
    const float* K    = (const float*)d_in[1];
    const int*   mask = (const int*)  d_in[2];
    const float* Wq   = (const float*)d_in[3];
    const float* bq   = (const float*)d_in[4];
    const float* Wk   = (const float*)d_in[5];
    const float* bk   = (const float*)d_in[6];
    const float* Wv   = (const float*)d_in[7];
    const float* bv   = (const float*)d_in[8];
    const float* Wo   = (const float*)d_in[9];
    const float* bo   = (const float*)d_in[10];
    float* out = (float*)d_out;

    float *pQ, *pK, *pV, *pO;
    cudaGetSymbolAddress((void**)&pQ, g_Qp);
    cudaGetSymbolAddress((void**)&pK, g_Kp);
    cudaGetSymbolAddress((void**)&pV, g_Vp);
    cudaGetSymbolAddress((void**)&pO, g_O);

    dim3 gG(DMODEL / 128, (BATCH * NQ) / 128);  // (8, 32)

    gemm_mma_kernel<<<gG, 256>>>(Q, Wq, bq, pQ);
    gemm_mma_kernel<<<gG, 256>>>(K, Wk, bk, pK);
    gemm_mma_kernel<<<gG, 256>>>(K, Wv, bv, pV);

    attn_mma_kernel<<<dim3(NQ / 128, NH, BATCH), 256>>>(mask);

    gemm_mma_kernel<<<gG, 256>>>(pO, Wo, bo, out);
}

// round 9
// speedup vs baseline: 3.2022x; 1.3447x over previous
#include <cuda_runtime.h>
#include <cuda_bf16.h>
#include <math.h>
#include <stdint.h>

#define BATCH   2
#define NQ      2048
#define NK      2048
#define DMODEL  1024
#define NH      16
#define HD      64
#define SCALE   (1.0f/32.0f)   // 1/sqrt(DIM_V)
#define EPSV    1e-8f

// Scratch — __device__ globals per allocation rules.
__device__ float g_Qp[(size_t)BATCH*NQ*DMODEL];
__device__ float g_Kp[(size_t)BATCH*NK*DMODEL];
__device__ float g_Vp[(size_t)BATCH*NK*DMODEL];
__device__ float g_O [(size_t)BATCH*NQ*DMODEL];

__device__ __forceinline__ uint32_t smem_u32(const void* p) {
    return (uint32_t)__cvta_generic_to_shared(p);
}
__device__ __forceinline__ uint32_t pack_bf2(float x, float y) {
    __nv_bfloat162 h = __floats2bfloat162_rn(x, y);
    return *reinterpret_cast<uint32_t*>(&h);
}
__device__ __forceinline__ void ldsm_x4(uint32_t& r0, uint32_t& r1, uint32_t& r2,
                                        uint32_t& r3, uint32_t addr) {
    asm volatile("ldmatrix.sync.aligned.m8n8.x4.shared.b16 {%0,%1,%2,%3}, [%4];"
                 : "=r"(r0), "=r"(r1), "=r"(r2), "=r"(r3) : "r"(addr));
}
__device__ __forceinline__ void ldsm_x4_t(uint32_t& r0, uint32_t& r1, uint32_t& r2,
                                          uint32_t& r3, uint32_t addr) {
    asm volatile("ldmatrix.sync.aligned.m8n8.x4.trans.shared.b16 {%0,%1,%2,%3}, [%4];"
                 : "=r"(r0), "=r"(r1), "=r"(r2), "=r"(r3) : "r"(addr));
}
#define MMA_BF16(c, a, b)                                                     \
    asm volatile("mma.sync.aligned.m16n8k16.row.col.f32.bf16.bf16.f32 "       \
                 "{%0,%1,%2,%3}, {%4,%5,%6,%7}, {%8,%9}, {%0,%1,%2,%3};"      \
                 : "+f"((c)[0]), "+f"((c)[1]), "+f"((c)[2]), "+f"((c)[3])     \
                 : "r"((a)[0]), "r"((a)[1]), "r"((a)[2]), "r"((a)[3]),        \
                   "r"((b)[0]), "r"((b)[1]))

// ---------------------------------------------------------------------------
// GEMM via mma.sync bf16 hi/lo split: C[M,N] = A[M,K] * W[N,K]^T + bias.
// R9: CTA tile 128x64, 8 warps (4m x 2n), warp tile 32x32, K-stage 32.
// ~32 accumulator regs/thread -> 2 CTAs/SM.
// ---------------------------------------------------------------------------
#define SSTRIDE 40   // bf16 elems per smem row (32 data + 8 pad) = 80 B

__global__ __launch_bounds__(256, 2)
void gemm_mma_kernel(const float* __restrict__ A, const float* __restrict__ W,
                     const float* __restrict__ bias, float* __restrict__ C)
{
    __shared__ __align__(16) __nv_bfloat16 sAhi[128 * SSTRIDE];
    __shared__ __align__(16) __nv_bfloat16 sAlo[128 * SSTRIDE];
    __shared__ __align__(16) __nv_bfloat16 sBhi[64 * SSTRIDE];
    __shared__ __align__(16) __nv_bfloat16 sBlo[64 * SSTRIDE];

    const int tid  = threadIdx.x;
    const int wid  = tid >> 5;
    const int lane = tid & 31;
    const int wm   = wid & 3;       // m offset wm*32
    const int wn   = wid >> 2;      // n offset wn*32
    const int bm   = blockIdx.y * 128, bn = blockIdx.x * 64;

    float c[2][4][4];
#pragma unroll
    for (int i = 0; i < 2; i++)
#pragma unroll
        for (int j = 0; j < 4; j++)
#pragma unroll
            for (int r = 0; r < 4; r++) c[i][j][r] = 0.f;

    // A ldmatrix.x4 (row-major): lane -> row (lane&15), k-half (lane>>4)
    const int a_row  = wm * 32 + (lane & 15);
    const int a_koff = (lane >> 4) * 16;
    const uint32_t aHiB = smem_u32(sAhi) + a_row * (SSTRIDE*2) + a_koff;
    const uint32_t aLoB = smem_u32(sAlo) + a_row * (SSTRIDE*2) + a_koff;
    // B ldmatrix.x4 covering 2 n8-tiles x 2 k-halves
    const int b_row  = wn * 32 + ((lane >> 4) * 8) + (lane & 7);
    const int b_koff = ((lane >> 3) & 1) * 16;
    const uint32_t bHiB = smem_u32(sBhi) + b_row * (SSTRIDE*2) + b_koff;
    const uint32_t bLoB = smem_u32(sBlo) + b_row * (SSTRIDE*2) + b_koff;

    for (int s = 0; s < DMODEL / 32; s++) {
        const int k0 = s * 32;
        // A tile [128 x 32]: 1024 float4, 4 per thread
#pragma unroll
        for (int it = 0; it < 4; it++) {
            int f   = tid + it * 256;
            int row = f >> 3;
            int c4  = (f & 7) * 4;
            float4 v = *(const float4*)(A + (size_t)(bm + row) * DMODEL + k0 + c4);
            float hx = __bfloat162float(__float2bfloat16_rn(v.x));
            float hy = __bfloat162float(__float2bfloat16_rn(v.y));
            float hz = __bfloat162float(__float2bfloat16_rn(v.z));
            float hw = __bfloat162float(__float2bfloat16_rn(v.w));
            *(uint2*)&sAhi[row * SSTRIDE + c4] =
                make_uint2(pack_bf2(hx, hy), pack_bf2(hz, hw));
            *(uint2*)&sAlo[row * SSTRIDE + c4] =
                make_uint2(pack_bf2(v.x - hx, v.y - hy), pack_bf2(v.z - hz, v.w - hw));
        }
        // B tile [64 x 32]: 512 float4, 2 per thread
#pragma unroll
        for (int it = 0; it < 2; it++) {
            int f   = tid + it * 256;
            int row = f >> 3;
            int c4  = (f & 7) * 4;
            float4 v = *(const float4*)(W + (size_t)(bn + row) * DMODEL + k0 + c4);
            float hx = __bfloat162float(__float2bfloat16_rn(v.x));
            float hy = __bfloat162float(__float2bfloat16_rn(v.y));
            float hz = __bfloat162float(__float2bfloat16_rn(v.z));
            float hw = __bfloat162float(__float2bfloat16_rn(v.w));
            *(uint2*)&sBhi[row * SSTRIDE + c4] =
                make_uint2(pack_bf2(hx, hy), pack_bf2(hz, hw));
            *(uint2*)&sBlo[row * SSTRIDE + c4] =
                make_uint2(pack_bf2(v.x - hx, v.y - hy), pack_bf2(v.z - hz, v.w - hw));
        }
        __syncthreads();

#pragma unroll
        for (int ks = 0; ks < 32; ks += 16) {
            uint32_t ah[2][4], al[2][4], bh[2][4], bl[2][4];
#pragma unroll
            for (int i = 0; i < 2; i++) {
                uint32_t off = (uint32_t)(i * 16 * (SSTRIDE*2) + ks * 2);
                ldsm_x4(ah[i][0], ah[i][1], ah[i][2], ah[i][3], aHiB + off);
                ldsm_x4(al[i][0], al[i][1], al[i][2], al[i][3], aLoB + off);
            }
#pragma unroll
            for (int jt = 0; jt < 2; jt++) {
                uint32_t off = (uint32_t)(jt * 16 * (SSTRIDE*2) + ks * 2);
                ldsm_x4(bh[jt][0], bh[jt][1], bh[jt][2], bh[jt][3], bHiB + off);
                ldsm_x4(bl[jt][0], bl[jt][1], bl[jt][2], bl[jt][3], bLoB + off);
            }
#pragma unroll
            for (int i = 0; i < 2; i++)
#pragma unroll
                for (int jt = 0; jt < 2; jt++)
#pragma unroll
                    for (int jj = 0; jj < 2; jj++) {
                        int j = jt * 2 + jj;
                        MMA_BF16(c[i][j], ah[i], &bh[jt][2*jj]);
                        MMA_BF16(c[i][j], ah[i], &bl[jt][2*jj]);
                        MMA_BF16(c[i][j], al[i], &bh[jt][2*jj]);
                    }
        }
        __syncthreads();
    }

    // Epilogue: bias + store
#pragma unroll
    for (int j = 0; j < 4; j++) {
        int col = bn + wn * 32 + j * 8 + (lane & 3) * 2;
        float bx = bias[col], by = bias[col + 1];
#pragma unroll
        for (int i = 0; i < 2; i++) {
            int row0 = bm + wm * 32 + i * 16 + (lane >> 2);
            *(float2*)(C + (size_t)row0 * DMODEL + col) =
                make_float2(c[i][j][0] + bx, c[i][j][1] + by);
            *(float2*)(C + (size_t)(row0 + 8) * DMODEL + col) =
                make_float2(c[i][j][2] + bx, c[i][j][3] + by);
        }
    }
}

// ---------------------------------------------------------------------------
// Flash attention via mma.sync (R8 structure, capped at 128 regs for 2 CTA/SM).
// ---------------------------------------------------------------------------
#define ASTR 72   // bf16 elems per smem row (64 data + 8 pad) = 144 B

__global__ __launch_bounds__(256, 2)
void attn_mma_kernel(const int* __restrict__ mask)
{
    __shared__ __align__(16) char sraw[3 * 64 * ASTR * 2];   // 27648 B
    __nv_bfloat16* sQ   = (__nv_bfloat16*)sraw;              // staging, pre-loop
    __nv_bfloat16* sK   = (__nv_bfloat16*)sraw;
    __nv_bfloat16* sVhi = (__nv_bfloat16*)(sraw + 64*ASTR*2);
    __nv_bfloat16* sVlo = (__nv_bfloat16*)(sraw + 2*64*ASTR*2);

    const int tid = threadIdx.x;
    const int w   = tid >> 5;
    const int L   = tid & 31;
    const int qr  = L >> 2;
    const int qc  = L & 3;
    const int q0  = blockIdx.x * 128;
    const int h   = blockIdx.y;
    const int b   = blockIdx.z;

    // ---- Stage Q tile [128 x 64], scaled by 1/32 ----
    {
        const float* Qb = g_Qp + ((size_t)b * NQ + q0) * DMODEL + h * HD;
#pragma unroll
        for (int it = 0; it < 8; it++) {
            int f   = tid + it * 256;
            int row = f >> 4;
            int c4  = (f & 15) * 4;
            float4 v = *(const float4*)(Qb + (size_t)row * DMODEL + c4);
            *(uint2*)&sQ[row * ASTR + c4] =
                make_uint2(pack_bf2(v.x * SCALE, v.y * SCALE),
                           pack_bf2(v.z * SCALE, v.w * SCALE));
        }
    }
    __syncthreads();

    uint32_t qa[4][4];
    {
        uint32_t base = smem_u32(sQ) + (w * 16 + (L & 15)) * (ASTR*2) + (L >> 4) * 16;
#pragma unroll
        for (int kk = 0; kk < 4; kk++)
            ldsm_x4(qa[kk][0], qa[kk][1], qa[kk][2], qa[kk][3], base + kk * 32);
    }
    __syncthreads();

    float m0 = -INFINITY, m1 = -INFINITY, l0 = 0.f, l1 = 0.f;
    float o[8][4];
#pragma unroll
    for (int j = 0; j < 8; j++)
#pragma unroll
        for (int r = 0; r < 4; r++) o[j][r] = 0.f;

    const int* mrow0 = mask + ((size_t)(b * NQ + q0 + w * 16 + qr)) * NK + 2 * qc;
    const int* mrow1 = mrow0 + (size_t)8 * NK;

    const uint32_t kB  = smem_u32(sK)   + (L & 7) * (ASTR*2) + (L >> 3) * 16;
    const uint32_t vHB = smem_u32(sVhi) + L * (ASTR*2);
    const uint32_t vLB = smem_u32(sVlo) + L * (ASTR*2);

    for (int kt = 0; kt < NK / 64; kt++) {
        const int k0 = kt * 64;
        {
            const float* Kb = g_Kp + ((size_t)b * NK + k0) * DMODEL + h * HD;
            const float* Vb = g_Vp + ((size_t)b * NK + k0) * DMODEL + h * HD;
#pragma unroll
            for (int it = 0; it < 4; it++) {
                int f   = tid + it * 256;
                int row = f >> 4;
                int c4  = (f & 15) * 4;
                float4 kv = *(const float4*)(Kb + (size_t)row * DMODEL + c4);
                *(uint2*)&sK[row * ASTR + c4] =
                    make_uint2(pack_bf2(kv.x, kv.y), pack_bf2(kv.z, kv.w));
                float4 vv = *(const float4*)(Vb + (size_t)row * DMODEL + c4);
                float hx = __bfloat162float(__float2bfloat16_rn(vv.x));
                float hy = __bfloat162float(__float2bfloat16_rn(vv.y));
                float hz = __bfloat162float(__float2bfloat16_rn(vv.z));
                float hw = __bfloat162float(__float2bfloat16_rn(vv.w));
                *(uint2*)&sVhi[row * ASTR + c4] =
                    make_uint2(pack_bf2(hx, hy), pack_bf2(hz, hw));
                *(uint2*)&sVlo[row * ASTR + c4] =
                    make_uint2(pack_bf2(vv.x - hx, vv.y - hy),
                               pack_bf2(vv.z - hz, vv.w - hw));
            }
        }
        __syncthreads();

        // ---- S = Q K^T ----
        float c[8][4];
#pragma unroll
        for (int j = 0; j < 8; j++) {
            uint32_t kb0[4], kb1[4];
            uint32_t a0 = kB + j * 8 * (ASTR*2);
            ldsm_x4(kb0[0], kb0[1], kb0[2], kb0[3], a0);
            ldsm_x4(kb1[0], kb1[1], kb1[2], kb1[3], a0 + 64);
            c[j][0] = c[j][1] = c[j][2] = c[j][3] = 0.f;
            MMA_BF16(c[j], qa[0], &kb0[0]);
            MMA_BF16(c[j], qa[1], &kb0[2]);
            MMA_BF16(c[j], qa[2], &kb1[0]);
            MMA_BF16(c[j], qa[3], &kb1[2]);
        }

        // ---- online softmax (pre-mask max) ----
        float mx0 = -INFINITY, mx1 = -INFINITY;
#pragma unroll
        for (int j = 0; j < 8; j++) {
            mx0 = fmaxf(mx0, fmaxf(c[j][0], c[j][1]));
            mx1 = fmaxf(mx1, fmaxf(c[j][2], c[j][3]));
        }
        mx0 = fmaxf(mx0, __shfl_xor_sync(0xffffffffu, mx0, 1));
        mx0 = fmaxf(mx0, __shfl_xor_sync(0xffffffffu, mx0, 2));
        mx1 = fmaxf(mx1, __shfl_xor_sync(0xffffffffu, mx1, 1));
        mx1 = fmaxf(mx1, __shfl_xor_sync(0xffffffffu, mx1, 2));
        float nm0 = fmaxf(m0, mx0), nm1 = fmaxf(m1, mx1);
        float f0 = __expf(m0 - nm0), f1 = __expf(m1 - nm1);
        l0 *= f0; l1 *= f1;
#pragma unroll
        for (int j = 0; j < 8; j++) {
            o[j][0] *= f0; o[j][1] *= f0; o[j][2] *= f1; o[j][3] *= f1;
        }
        m0 = nm0; m1 = nm1;

        // ---- P = mask ? exp(S-m) : 0 ; hi/lo fragments ----
        uint32_t ph[4][4], pl[4][4];
#pragma unroll
        for (int kk = 0; kk < 4; kk++) {
#pragma unroll
            for (int hh = 0; hh < 2; hh++) {
                int j = kk * 2 + hh;
                int2 mv0 = *(const int2*)(mrow0 + k0 + 8 * j);
                int2 mv1 = *(const int2*)(mrow1 + k0 + 8 * j);
                float p0 = mv0.x ? __expf(c[j][0] - m0) : 0.f;
                float p1 = mv0.y ? __expf(c[j][1] - m0) : 0.f;
                float p2 = mv1.x ? __expf(c[j][2] - m1) : 0.f;
                float p3 = mv1.y ? __expf(c[j][3] - m1) : 0.f;
                l0 += p0 + p1; l1 += p2 + p3;
                float h0 = __bfloat162float(__float2bfloat16_rn(p0));
                float h1 = __bfloat162float(__float2bfloat16_rn(p1));
                float h2 = __bfloat162float(__float2bfloat16_rn(p2));
                float h3 = __bfloat162float(__float2bfloat16_rn(p3));
                ph[kk][2*hh]   = pack_bf2(p0, p1);
                ph[kk][2*hh+1] = pack_bf2(p2, p3);
                pl[kk][2*hh]   = pack_bf2(p0 - h0, p1 - h1);
                pl[kk][2*hh+1] = pack_bf2(p2 - h2, p3 - h3);
            }
        }

        // ---- O += P * V (hi/lo split) ----
#pragma unroll
        for (int j = 0; j < 8; j++) {
            uint32_t vh0[4], vh1[4], vl0[4], vl1[4];
            ldsm_x4_t(vh0[0], vh0[1], vh0[2], vh0[3], vHB + j * 16);
            ldsm_x4_t(vh1[0], vh1[1], vh1[2], vh1[3], vHB + 32 * (ASTR*2) + j * 16);
            ldsm_x4_t(vl0[0], vl0[1], vl0[2], vl0[3], vLB + j * 16);
            ldsm_x4_t(vl1[0], vl1[1], vl1[2], vl1[3], vLB + 32 * (ASTR*2) + j * 16);
            MMA_BF16(o[j], ph[0], &vh0[0]);
            MMA_BF16(o[j], ph[1], &vh0[2]);
            MMA_BF16(o[j], ph[2], &vh1[0]);
            MMA_BF16(o[j], ph[3], &vh1[2]);
            MMA_BF16(o[j], ph[0], &vl0[0]);
            MMA_BF16(o[j], ph[1], &vl0[2]);
            MMA_BF16(o[j], ph[2], &vl1[0]);
            MMA_BF16(o[j], ph[3], &vl1[2]);
            MMA_BF16(o[j], pl[0], &vh0[0]);
            MMA_BF16(o[j], pl[1], &vh0[2]);
            MMA_BF16(o[j], pl[2], &vh1[0]);
            MMA_BF16(o[j], pl[3], &vh1[2]);
        }
        __syncthreads();
    }

    // ---- finalize ----
    l0 += __shfl_xor_sync(0xffffffffu, l0, 1);
    l0 += __shfl_xor_sync(0xffffffffu, l0, 2);
    l1 += __shfl_xor_sync(0xffffffffu, l1, 1);
    l1 += __shfl_xor_sync(0xffffffffu, l1, 2);
    float inv0 = 1.f / (l0 + EPSV);
    float inv1 = 1.f / (l1 + EPSV);

    float* Ob = g_O + ((size_t)b * NQ + q0 + w * 16) * DMODEL + h * HD;
#pragma unroll
    for (int j = 0; j < 8; j++) {
        int col = 8 * j + 2 * qc;
        *(float2*)(Ob + (size_t)qr * DMODEL + col) =
            make_float2(o[j][0] * inv0, o[j][1] * inv0);
        *(float2*)(Ob + (size_t)(qr + 8) * DMODEL + col) =
            make_float2(o[j][2] * inv1, o[j][3] * inv1);
    }
}

// ---------------------------------------------------------------------------
extern "C" void kernel_launch(void* const* d_in, const int* in_sizes, int n_in,
                              void* d_out, int out_size)
{
    const float* Q    = (const float*)d_in[0];
    const float* K    = (const float*)d_in[1];
    const int*   mask = (const int*)  d_in[2];
    const float* Wq   = (const float*)d_in[3];
    const float* bq   = (const float*)d_in[4];
    const float* Wk   = (const float*)d_in[5];
    const float* bk   = (const float*)d_in[6];
    const float* Wv   = (const float*)d_in[7];
    const float* bv   = (const float*)d_in[8];
    const float* Wo   = (const float*)d_in[9];
    const float* bo   = (const float*)d_in[10];
    float* out = (float*)d_out;

    float *pQ, *pK, *pV, *pO;
    cudaGetSymbolAddress((void**)&pQ, g_Qp);
    cudaGetSymbolAddress((void**)&pK, g_Kp);
    cudaGetSymbolAddress((void**)&pV, g_Vp);
    cudaGetSymbolAddress((void**)&pO, g_O);

    dim3 gG(DMODEL / 64, (BATCH * NQ) / 128);  // (16, 32) = 512 CTAs

    gemm_mma_kernel<<<gG, 256>>>(Q, Wq, bq, pQ);
    gemm_mma_kernel<<<gG, 256>>>(K, Wk, bk, pK);
    gemm_mma_kernel<<<gG, 256>>>(K, Wv, bv, pV);

    attn_mma_kernel<<<dim3(NQ / 128, NH, BATCH), 256>>>(mask);

    gemm_mma_kernel<<<gG, 256>>>(pO, Wo, bo, out);
}

// round 11
// speedup vs baseline: 3.8067x; 1.1888x over previous
#include <cuda_runtime.h>
#include <cuda_bf16.h>
#include <math.h>
#include <stdint.h>

#define BATCH   2
#define NQ      2048
#define NK      2048
#define DMODEL  1024
#define NH      16
#define HD      64
#define SCALE   (1.0f/32.0f)   // 1/sqrt(DIM_V)
#define EPSV    1e-8f

// Scratch — __device__ globals per allocation rules.
__device__ __nv_bfloat16 g_Qb [(size_t)BATCH*NQ*DMODEL];   // Q proj, pre-scaled, bf16
__device__ __nv_bfloat16 g_Kb [(size_t)BATCH*NK*DMODEL];   // K proj, bf16
__device__ __nv_bfloat16 g_Vhi[(size_t)BATCH*NK*DMODEL];   // V proj hi
__device__ __nv_bfloat16 g_Vlo[(size_t)BATCH*NK*DMODEL];   // V proj lo
__device__ float         g_O  [(size_t)BATCH*NQ*DMODEL];   // attn out, fp32

__device__ __forceinline__ uint32_t smem_u32(const void* p) {
    return (uint32_t)__cvta_generic_to_shared(p);
}
__device__ __forceinline__ uint32_t pack_bf2(float x, float y) {
    __nv_bfloat162 h = __floats2bfloat162_rn(x, y);
    return *reinterpret_cast<uint32_t*>(&h);
}
__device__ __forceinline__ void ldsm_x4(uint32_t& r0, uint32_t& r1, uint32_t& r2,
                                        uint32_t& r3, uint32_t addr) {
    asm volatile("ldmatrix.sync.aligned.m8n8.x4.shared.b16 {%0,%1,%2,%3}, [%4];"
                 : "=r"(r0), "=r"(r1), "=r"(r2), "=r"(r3) : "r"(addr));
}
__device__ __forceinline__ void ldsm_x4_t(uint32_t& r0, uint32_t& r1, uint32_t& r2,
                                          uint32_t& r3, uint32_t addr) {
    asm volatile("ldmatrix.sync.aligned.m8n8.x4.trans.shared.b16 {%0,%1,%2,%3}, [%4];"
                 : "=r"(r0), "=r"(r1), "=r"(r2), "=r"(r3) : "r"(addr));
}
#define MMA_BF16(c, a, b)                                                     \
    asm volatile("mma.sync.aligned.m16n8k16.row.col.f32.bf16.bf16.f32 "       \
                 "{%0,%1,%2,%3}, {%4,%5,%6,%7}, {%8,%9}, {%0,%1,%2,%3};"      \
                 : "+f"((c)[0]), "+f"((c)[1]), "+f"((c)[2]), "+f"((c)[3])     \
                 : "r"((a)[0]), "r"((a)[1]), "r"((a)[2]), "r"((a)[3]),        \
                   "r"((b)[0]), "r"((b)[1]))

// ---------------------------------------------------------------------------
// GEMM via mma.sync: C = A[M,K] * W[N,K]^T + bias. CTA 128x64, warp 32x32.
// NT = 1 (single bf16 pass) or 3 (hi/lo split).
// OM = 0: fp32 out; 1: bf16 out (scaled); 2: bf16 hi/lo out.
// ---------------------------------------------------------------------------
#define SSTRIDE 40   // bf16 elems per smem row (32 data + 8 pad) = 80 B

template<int NT, int OM>
__global__ __launch_bounds__(256, 2)
void gemm_mma(const float* __restrict__ A, const float* __restrict__ W,
              const float* __restrict__ bias, float* __restrict__ C32,
              __nv_bfloat16* __restrict__ Cb, __nv_bfloat16* __restrict__ Cb2,
              float oscale)
{
    __shared__ __align__(16) __nv_bfloat16 sAhi[128 * SSTRIDE];
    __shared__ __align__(16) __nv_bfloat16 sAlo[128 * SSTRIDE];
    __shared__ __align__(16) __nv_bfloat16 sBhi[64 * SSTRIDE];
    __shared__ __align__(16) __nv_bfloat16 sBlo[64 * SSTRIDE];

    const int tid  = threadIdx.x;
    const int wid  = tid >> 5;
    const int lane = tid & 31;
    const int wm   = wid & 3;
    const int wn   = wid >> 2;
    const int bm   = blockIdx.y * 128, bn = blockIdx.x * 64;

    float c[2][4][4];
#pragma unroll
    for (int i = 0; i < 2; i++)
#pragma unroll
        for (int j = 0; j < 4; j++)
#pragma unroll
            for (int r = 0; r < 4; r++) c[i][j][r] = 0.f;

    const int a_row  = wm * 32 + (lane & 15);
    const int a_koff = (lane >> 4) * 16;
    const uint32_t aHiB = smem_u32(sAhi) + a_row * (SSTRIDE*2) + a_koff;
    const uint32_t aLoB = smem_u32(sAlo) + a_row * (SSTRIDE*2) + a_koff;
    const int b_row  = wn * 32 + ((lane >> 4) * 8) + (lane & 7);
    const int b_koff = ((lane >> 3) & 1) * 16;
    const uint32_t bHiB = smem_u32(sBhi) + b_row * (SSTRIDE*2) + b_koff;
    const uint32_t bLoB = smem_u32(sBlo) + b_row * (SSTRIDE*2) + b_koff;

    for (int s = 0; s < DMODEL / 32; s++) {
        const int k0 = s * 32;
#pragma unroll
        for (int it = 0; it < 4; it++) {
            int f   = tid + it * 256;
            int row = f >> 3;
            int c4  = (f & 7) * 4;
            float4 v = *(const float4*)(A + (size_t)(bm + row) * DMODEL + k0 + c4);
            if (NT == 3) {
                float hx = __bfloat162float(__float2bfloat16_rn(v.x));
                float hy = __bfloat162float(__float2bfloat16_rn(v.y));
                float hz = __bfloat162float(__float2bfloat16_rn(v.z));
                float hw = __bfloat162float(__float2bfloat16_rn(v.w));
                *(uint2*)&sAhi[row * SSTRIDE + c4] =
                    make_uint2(pack_bf2(hx, hy), pack_bf2(hz, hw));
                *(uint2*)&sAlo[row * SSTRIDE + c4] =
                    make_uint2(pack_bf2(v.x - hx, v.y - hy), pack_bf2(v.z - hz, v.w - hw));
            } else {
                *(uint2*)&sAhi[row * SSTRIDE + c4] =
                    make_uint2(pack_bf2(v.x, v.y), pack_bf2(v.z, v.w));
            }
        }
#pragma unroll
        for (int it = 0; it < 2; it++) {
            int f   = tid + it * 256;
            int row = f >> 3;
            int c4  = (f & 7) * 4;
            float4 v = *(const float4*)(W + (size_t)(bn + row) * DMODEL + k0 + c4);
            if (NT == 3) {
                float hx = __bfloat162float(__float2bfloat16_rn(v.x));
                float hy = __bfloat162float(__float2bfloat16_rn(v.y));
                float hz = __bfloat162float(__float2bfloat16_rn(v.z));
                float hw = __bfloat162float(__float2bfloat16_rn(v.w));
                *(uint2*)&sBhi[row * SSTRIDE + c4] =
                    make_uint2(pack_bf2(hx, hy), pack_bf2(hz, hw));
                *(uint2*)&sBlo[row * SSTRIDE + c4] =
                    make_uint2(pack_bf2(v.x - hx, v.y - hy), pack_bf2(v.z - hz, v.w - hw));
            } else {
                *(uint2*)&sBhi[row * SSTRIDE + c4] =
                    make_uint2(pack_bf2(v.x, v.y), pack_bf2(v.z, v.w));
            }
        }
        __syncthreads();

#pragma unroll
        for (int ks = 0; ks < 32; ks += 16) {
            uint32_t ah[2][4], al[2][4], bh[2][4], bl[2][4];
#pragma unroll
            for (int i = 0; i < 2; i++) {
                uint32_t off = (uint32_t)(i * 16 * (SSTRIDE*2) + ks * 2);
                ldsm_x4(ah[i][0], ah[i][1], ah[i][2], ah[i][3], aHiB + off);
                if (NT == 3)
                    ldsm_x4(al[i][0], al[i][1], al[i][2], al[i][3], aLoB + off);
            }
#pragma unroll
            for (int jt = 0; jt < 2; jt++) {
                uint32_t off = (uint32_t)(jt * 16 * (SSTRIDE*2) + ks * 2);
                ldsm_x4(bh[jt][0], bh[jt][1], bh[jt][2], bh[jt][3], bHiB + off);
                if (NT == 3)
                    ldsm_x4(bl[jt][0], bl[jt][1], bl[jt][2], bl[jt][3], bLoB + off);
            }
#pragma unroll
            for (int i = 0; i < 2; i++)
#pragma unroll
                for (int jt = 0; jt < 2; jt++)
#pragma unroll
                    for (int jj = 0; jj < 2; jj++) {
                        int j = jt * 2 + jj;
                        MMA_BF16(c[i][j], ah[i], &bh[jt][2*jj]);
                        if (NT == 3) {
                            MMA_BF16(c[i][j], ah[i], &bl[jt][2*jj]);
                            MMA_BF16(c[i][j], al[i], &bh[jt][2*jj]);
                        }
                    }
        }
        __syncthreads();
    }

    // Epilogue
#pragma unroll
    for (int j = 0; j < 4; j++) {
        int col = bn + wn * 32 + j * 8 + (lane & 3) * 2;
        float bx = bias[col], by = bias[col + 1];
#pragma unroll
        for (int i = 0; i < 2; i++) {
            int row0 = bm + wm * 32 + i * 16 + (lane >> 2);
            float v0 = c[i][j][0] + bx, v1 = c[i][j][1] + by;
            float v2 = c[i][j][2] + bx, v3 = c[i][j][3] + by;
            if (OM == 0) {
                *(float2*)(C32 + (size_t)row0 * DMODEL + col)       = make_float2(v0, v1);
                *(float2*)(C32 + (size_t)(row0 + 8) * DMODEL + col) = make_float2(v2, v3);
            } else if (OM == 1) {
                *(uint32_t*)(Cb + (size_t)row0 * DMODEL + col)       = pack_bf2(v0*oscale, v1*oscale);
                *(uint32_t*)(Cb + (size_t)(row0 + 8) * DMODEL + col) = pack_bf2(v2*oscale, v3*oscale);
            } else {
                float h0 = __bfloat162float(__float2bfloat16_rn(v0));
                float h1 = __bfloat162float(__float2bfloat16_rn(v1));
                float h2 = __bfloat162float(__float2bfloat16_rn(v2));
                float h3 = __bfloat162float(__float2bfloat16_rn(v3));
                *(uint32_t*)(Cb  + (size_t)row0 * DMODEL + col)       = pack_bf2(h0, h1);
                *(uint32_t*)(Cb  + (size_t)(row0 + 8) * DMODEL + col) = pack_bf2(h2, h3);
                *(uint32_t*)(Cb2 + (size_t)row0 * DMODEL + col)       = pack_bf2(v0 - h0, v1 - h1);
                *(uint32_t*)(Cb2 + (size_t)(row0 + 8) * DMODEL + col) = pack_bf2(v2 - h2, v3 - h3);
            }
        }
    }
}

// ---------------------------------------------------------------------------
// Flash attention via mma.sync. Operands pre-converted to bf16 by the
// projection epilogues -> inner loop is pure copy + LDSM + MMA + softmax.
// ---------------------------------------------------------------------------
#define ASTR 72   // bf16 elems per smem row (64 data + 8 pad) = 144 B

__global__ __launch_bounds__(256, 2)
void attn_mma_kernel(const int* __restrict__ mask)
{
    __shared__ __align__(16) char sraw[3 * 64 * ASTR * 2];   // 27648 B
    __nv_bfloat16* sQ   = (__nv_bfloat16*)sraw;              // staging (pre-loop)
    __nv_bfloat16* sK   = (__nv_bfloat16*)sraw;
    __nv_bfloat16* sVhi = (__nv_bfloat16*)(sraw + 64*ASTR*2);
    __nv_bfloat16* sVlo = (__nv_bfloat16*)(sraw + 2*64*ASTR*2);

    const int tid = threadIdx.x;
    const int w   = tid >> 5;
    const int L   = tid & 31;
    const int qr  = L >> 2;
    const int qc  = L & 3;
    const int q0  = blockIdx.x * 128;
    const int h   = blockIdx.y;
    const int b   = blockIdx.z;

    // ---- Stage Q tile [128 x 64] bf16 (already scaled) ----
    {
        const __nv_bfloat16* Qb = g_Qb + ((size_t)b * NQ + q0) * DMODEL + h * HD;
#pragma unroll
        for (int it = 0; it < 4; it++) {
            int f   = tid + it * 256;       // 1024 chunks of 8 bf16
            int row = f >> 3;
            int c8  = (f & 7) * 8;
            *(uint4*)&sQ[row * ASTR + c8] =
                *(const uint4*)(Qb + (size_t)row * DMODEL + c8);
        }
    }
    __syncthreads();

    uint32_t qa[4][4];
    {
        uint32_t base = smem_u32(sQ) + (w * 16 + (L & 15)) * (ASTR*2) + (L >> 4) * 16;
#pragma unroll
        for (int kk = 0; kk < 4; kk++)
            ldsm_x4(qa[kk][0], qa[kk][1], qa[kk][2], qa[kk][3], base + kk * 32);
    }
    __syncthreads();

    float m0 = -INFINITY, m1 = -INFINITY, l0 = 0.f, l1 = 0.f;
    float o[8][4];
#pragma unroll
    for (int j = 0; j < 8; j++)
#pragma unroll
        for (int r = 0; r < 4; r++) o[j][r] = 0.f;

    const int* mrow0 = mask + ((size_t)(b * NQ + q0 + w * 16 + qr)) * NK + 2 * qc;
    const int* mrow1 = mrow0 + (size_t)8 * NK;

    const uint32_t kB  = smem_u32(sK)   + (L & 7) * (ASTR*2) + (L >> 3) * 16;
    const uint32_t vHB = smem_u32(sVhi) + L * (ASTR*2);
    const uint32_t vLB = smem_u32(sVlo) + L * (ASTR*2);

    for (int kt = 0; kt < NK / 64; kt++) {
        const int k0 = kt * 64;
        // ---- load K / Vhi / Vlo tiles [64 x 64] bf16: pure 16B copies ----
        {
            const __nv_bfloat16* Kb = g_Kb  + ((size_t)b * NK + k0) * DMODEL + h * HD;
            const __nv_bfloat16* Vh = g_Vhi + ((size_t)b * NK + k0) * DMODEL + h * HD;
            const __nv_bfloat16* Vl = g_Vlo + ((size_t)b * NK + k0) * DMODEL + h * HD;
#pragma unroll
            for (int it = 0; it < 2; it++) {
                int f   = tid + it * 256;       // 512 chunks per tile
                int row = f >> 3;
                int c8  = (f & 7) * 8;
                size_t g = (size_t)row * DMODEL + c8;
                int sidx = row * ASTR + c8;
                *(uint4*)&sK[sidx]   = *(const uint4*)(Kb + g);
                *(uint4*)&sVhi[sidx] = *(const uint4*)(Vh + g);
                *(uint4*)&sVlo[sidx] = *(const uint4*)(Vl + g);
            }
        }
        __syncthreads();

        // ---- S = Q K^T ----
        float c[8][4];
#pragma unroll
        for (int j = 0; j < 8; j++) {
            uint32_t kb0[4], kb1[4];
            uint32_t a0 = kB + j * 8 * (ASTR*2);
            ldsm_x4(kb0[0], kb0[1], kb0[2], kb0[3], a0);
            ldsm_x4(kb1[0], kb1[1], kb1[2], kb1[3], a0 + 64);
            c[j][0] = c[j][1] = c[j][2] = c[j][3] = 0.f;
            MMA_BF16(c[j], qa[0], &kb0[0]);
            MMA_BF16(c[j], qa[1], &kb0[2]);
            MMA_BF16(c[j], qa[2], &kb1[0]);
            MMA_BF16(c[j], qa[3], &kb1[2]);
        }

        // ---- online softmax (pre-mask max) ----
        float mx0 = -INFINITY, mx1 = -INFINITY;
#pragma unroll
        for (int j = 0; j < 8; j++) {
            mx0 = fmaxf(mx0, fmaxf(c[j][0], c[j][1]));
            mx1 = fmaxf(mx1, fmaxf(c[j][2], c[j][3]));
        }
        mx0 = fmaxf(mx0, __shfl_xor_sync(0xffffffffu, mx0, 1));
        mx0 = fmaxf(mx0, __shfl_xor_sync(0xffffffffu, mx0, 2));
        mx1 = fmaxf(mx1, __shfl_xor_sync(0xffffffffu, mx1, 1));
        mx1 = fmaxf(mx1, __shfl_xor_sync(0xffffffffu, mx1, 2));
        float nm0 = fmaxf(m0, mx0), nm1 = fmaxf(m1, mx1);
        float f0 = __expf(m0 - nm0), f1 = __expf(m1 - nm1);
        l0 *= f0; l1 *= f1;
#pragma unroll
        for (int j = 0; j < 8; j++) {
            o[j][0] *= f0; o[j][1] *= f0; o[j][2] *= f1; o[j][3] *= f1;
        }
        m0 = nm0; m1 = nm1;

        // ---- P = mask ? exp(S-m) : 0 ; hi/lo fragments ----
        uint32_t ph[4][4], pl[4][4];
#pragma unroll
        for (int kk = 0; kk < 4; kk++) {
#pragma unroll
            for (int hh = 0; hh < 2; hh++) {
                int j = kk * 2 + hh;
                int2 mv0 = *(const int2*)(mrow0 + k0 + 8 * j);
                int2 mv1 = *(const int2*)(mrow1 + k0 + 8 * j);
                float p0 = mv0.x ? __expf(c[j][0] - m0) : 0.f;
                float p1 = mv0.y ? __expf(c[j][1] - m0) : 0.f;
                float p2 = mv1.x ? __expf(c[j][2] - m1) : 0.f;
                float p3 = mv1.y ? __expf(c[j][3] - m1) : 0.f;
                l0 += p0 + p1; l1 += p2 + p3;
                float h0 = __bfloat162float(__float2bfloat16_rn(p0));
                float h1 = __bfloat162float(__float2bfloat16_rn(p1));
                float h2 = __bfloat162float(__float2bfloat16_rn(p2));
                float h3 = __bfloat162float(__float2bfloat16_rn(p3));
                ph[kk][2*hh]   = pack_bf2(p0, p1);
                ph[kk][2*hh+1] = pack_bf2(p2, p3);
                pl[kk][2*hh]   = pack_bf2(p0 - h0, p1 - h1);
                pl[kk][2*hh+1] = pack_bf2(p2 - h2, p3 - h3);
            }
        }

        // ---- O += P * V (hi/lo split) ----
#pragma unroll
        for (int j = 0; j < 8; j++) {
            uint32_t vh0[4], vh1[4], vl0[4], vl1[4];
            ldsm_x4_t(vh0[0], vh0[1], vh0[2], vh0[3], vHB + j * 16);
            ldsm_x4_t(vh1[0], vh1[1], vh1[2], vh1[3], vHB + 32 * (ASTR*2) + j * 16);
            ldsm_x4_t(vl0[0], vl0[1], vl0[2], vl0[3], vLB + j * 16);
            ldsm_x4_t(vl1[0], vl1[1], vl1[2], vl1[3], vLB + 32 * (ASTR*2) + j * 16);
            MMA_BF16(o[j], ph[0], &vh0[0]);
            MMA_BF16(o[j], ph[1], &vh0[2]);
            MMA_BF16(o[j], ph[2], &vh1[0]);
            MMA_BF16(o[j], ph[3], &vh1[2]);
            MMA_BF16(o[j], ph[0], &vl0[0]);
            MMA_BF16(o[j], ph[1], &vl0[2]);
            MMA_BF16(o[j], ph[2], &vl1[0]);
            MMA_BF16(o[j], ph[3], &vl1[2]);
            MMA_BF16(o[j], pl[0], &vh0[0]);
            MMA_BF16(o[j], pl[1], &vh0[2]);
            MMA_BF16(o[j], pl[2], &vh1[0]);
            MMA_BF16(o[j], pl[3], &vh1[2]);
        }
        __syncthreads();
    }

    // ---- finalize ----
    l0 += __shfl_xor_sync(0xffffffffu, l0, 1);
    l0 += __shfl_xor_sync(0xffffffffu, l0, 2);
    l1 += __shfl_xor_sync(0xffffffffu, l1, 1);
    l1 += __shfl_xor_sync(0xffffffffu, l1, 2);
    float inv0 = 1.f / (l0 + EPSV);
    float inv1 = 1.f / (l1 + EPSV);

    float* Ob = g_O + ((size_t)b * NQ + q0 + w * 16) * DMODEL + h * HD;
#pragma unroll
    for (int j = 0; j < 8; j++) {
        int col = 8 * j + 2 * qc;
        *(float2*)(Ob + (size_t)qr * DMODEL + col) =
            make_float2(o[j][0] * inv0, o[j][1] * inv0);
        *(float2*)(Ob + (size_t)(qr + 8) * DMODEL + col) =
            make_float2(o[j][2] * inv1, o[j][3] * inv1);
    }
}

// ---------------------------------------------------------------------------
extern "C" void kernel_launch(void* const* d_in, const int* in_sizes, int n_in,
                              void* d_out, int out_size)
{
    const float* Q    = (const float*)d_in[0];
    const float* K    = (const float*)d_in[1];
    const int*   mask = (const int*)  d_in[2];
    const float* Wq   = (const float*)d_in[3];
    const float* bq   = (const float*)d_in[4];
    const float* Wk   = (const float*)d_in[5];
    const float* bk   = (const float*)d_in[6];
    const float* Wv   = (const float*)d_in[7];
    const float* bv   = (const float*)d_in[8];
    const float* Wo   = (const float*)d_in[9];
    const float* bo   = (const float*)d_in[10];
    float* out = (float*)d_out;

    __nv_bfloat16 *pQb, *pKb, *pVhi, *pVlo;
    float *pO;
    cudaGetSymbolAddress((void**)&pQb,  g_Qb);
    cudaGetSymbolAddress((void**)&pKb,  g_Kb);
    cudaGetSymbolAddress((void**)&pVhi, g_Vhi);
    cudaGetSymbolAddress((void**)&pVlo, g_Vlo);
    cudaGetSymbolAddress((void**)&pO,   g_O);

    dim3 gG(DMODEL / 64, (BATCH * NQ) / 128);  // (16, 32) = 512 CTAs

    gemm_mma<1,1><<<gG, 256>>>(Q, Wq, bq, nullptr, pQb, nullptr, SCALE);  // Q proj -> bf16 scaled
    gemm_mma<1,1><<<gG, 256>>>(K, Wk, bk, nullptr, pKb, nullptr, 1.0f);   // K proj -> bf16
    gemm_mma<3,2><<<gG, 256>>>(K, Wv, bv, nullptr, pVhi, pVlo, 1.0f);     // V proj -> bf16 hi/lo

    attn_mma_kernel<<<dim3(NQ / 128, NH, BATCH), 256>>>(mask);

    gemm_mma<3,0><<<gG, 256>>>(pO, Wo, bo, out, nullptr, nullptr, 1.0f);  // O proj -> fp32
}

// round 12
// speedup vs baseline: 3.9558x; 1.0391x over previous
#include <cuda_runtime.h>
#include <cuda_bf16.h>
#include <cuda_fp16.h>
#include <math.h>
#include <stdint.h>

#define BATCH   2
#define NQ      2048
#define NK      2048
#define DMODEL  1024
#define NH      16
#define HD      64
#define SCALE   (1.0f/32.0f)   // 1/sqrt(DIM_V)
#define EPSV    1e-8f

// Scratch — __device__ globals per allocation rules.
__device__ __nv_bfloat16 g_Qb[(size_t)BATCH*NQ*DMODEL];   // Q proj, pre-scaled, bf16
__device__ __nv_bfloat16 g_Kb[(size_t)BATCH*NK*DMODEL];   // K proj, bf16
__device__ __half        g_Vh[(size_t)BATCH*NK*DMODEL];   // V proj, fp16
__device__ float         g_O [(size_t)BATCH*NQ*DMODEL];   // attn out, fp32

__device__ __forceinline__ uint32_t smem_u32(const void* p) {
    return (uint32_t)__cvta_generic_to_shared(p);
}
__device__ __forceinline__ uint32_t pack_bf2(float x, float y) {
    __nv_bfloat162 h = __floats2bfloat162_rn(x, y);
    return *reinterpret_cast<uint32_t*>(&h);
}
__device__ __forceinline__ uint32_t pack_h2(float x, float y) {
    __half2 h = __floats2half2_rn(x, y);
    return *reinterpret_cast<uint32_t*>(&h);
}
__device__ __forceinline__ void ldsm_x4(uint32_t& r0, uint32_t& r1, uint32_t& r2,
                                        uint32_t& r3, uint32_t addr) {
    asm volatile("ldmatrix.sync.aligned.m8n8.x4.shared.b16 {%0,%1,%2,%3}, [%4];"
                 : "=r"(r0), "=r"(r1), "=r"(r2), "=r"(r3) : "r"(addr));
}
__device__ __forceinline__ void ldsm_x4_t(uint32_t& r0, uint32_t& r1, uint32_t& r2,
                                          uint32_t& r3, uint32_t addr) {
    asm volatile("ldmatrix.sync.aligned.m8n8.x4.trans.shared.b16 {%0,%1,%2,%3}, [%4];"
                 : "=r"(r0), "=r"(r1), "=r"(r2), "=r"(r3) : "r"(addr));
}
#define MMA_BF16(c, a, b)                                                     \
    asm volatile("mma.sync.aligned.m16n8k16.row.col.f32.bf16.bf16.f32 "       \
                 "{%0,%1,%2,%3}, {%4,%5,%6,%7}, {%8,%9}, {%0,%1,%2,%3};"      \
                 : "+f"((c)[0]), "+f"((c)[1]), "+f"((c)[2]), "+f"((c)[3])     \
                 : "r"((a)[0]), "r"((a)[1]), "r"((a)[2]), "r"((a)[3]),        \
                   "r"((b)[0]), "r"((b)[1]))
#define MMA_FP16(c, a, b)                                                     \
    asm volatile("mma.sync.aligned.m16n8k16.row.col.f32.f16.f16.f32 "         \
                 "{%0,%1,%2,%3}, {%4,%5,%6,%7}, {%8,%9}, {%0,%1,%2,%3};"      \
                 : "+f"((c)[0]), "+f"((c)[1]), "+f"((c)[2]), "+f"((c)[3])     \
                 : "r"((a)[0]), "r"((a)[1]), "r"((a)[2]), "r"((a)[3]),        \
                   "r"((b)[0]), "r"((b)[1]))

// ---------------------------------------------------------------------------
// GEMM via mma.sync: C = A[M,K] * W[N,K]^T + bias. CTA 128x64, warp 32x32.
// NT = 1 (single bf16 pass) or 3 (hi/lo split).
// OM = 0: fp32 out; 1: bf16 out (scaled); 3: fp16 out.
// ---------------------------------------------------------------------------
#define SSTRIDE 40   // bf16 elems per smem row (32 data + 8 pad) = 80 B

template<int NT, int OM>
__global__ __launch_bounds__(256, 2)
void gemm_mma(const float* __restrict__ A, const float* __restrict__ W,
              const float* __restrict__ bias, float* __restrict__ C32,
              __nv_bfloat16* __restrict__ Cb, __half* __restrict__ Ch,
              float oscale)
{
    __shared__ __align__(16) __nv_bfloat16 sAhi[128 * SSTRIDE];
    __shared__ __align__(16) __nv_bfloat16 sAlo[128 * SSTRIDE];
    __shared__ __align__(16) __nv_bfloat16 sBhi[64 * SSTRIDE];
    __shared__ __align__(16) __nv_bfloat16 sBlo[64 * SSTRIDE];

    const int tid  = threadIdx.x;
    const int wid  = tid >> 5;
    const int lane = tid & 31;
    const int wm   = wid & 3;
    const int wn   = wid >> 2;
    const int bm   = blockIdx.y * 128, bn = blockIdx.x * 64;

    float c[2][4][4];
#pragma unroll
    for (int i = 0; i < 2; i++)
#pragma unroll
        for (int j = 0; j < 4; j++)
#pragma unroll
            for (int r = 0; r < 4; r++) c[i][j][r] = 0.f;

    const int a_row  = wm * 32 + (lane & 15);
    const int a_koff = (lane >> 4) * 16;
    const uint32_t aHiB = smem_u32(sAhi) + a_row * (SSTRIDE*2) + a_koff;
    const uint32_t aLoB = smem_u32(sAlo) + a_row * (SSTRIDE*2) + a_koff;
    const int b_row  = wn * 32 + ((lane >> 4) * 8) + (lane & 7);
    const int b_koff = ((lane >> 3) & 1) * 16;
    const uint32_t bHiB = smem_u32(sBhi) + b_row * (SSTRIDE*2) + b_koff;
    const uint32_t bLoB = smem_u32(sBlo) + b_row * (SSTRIDE*2) + b_koff;

    for (int s = 0; s < DMODEL / 32; s++) {
        const int k0 = s * 32;
#pragma unroll
        for (int it = 0; it < 4; it++) {
            int f   = tid + it * 256;
            int row = f >> 3;
            int c4  = (f & 7) * 4;
            float4 v = *(const float4*)(A + (size_t)(bm + row) * DMODEL + k0 + c4);
            if (NT == 3) {
                float hx = __bfloat162float(__float2bfloat16_rn(v.x));
                float hy = __bfloat162float(__float2bfloat16_rn(v.y));
                float hz = __bfloat162float(__float2bfloat16_rn(v.z));
                float hw = __bfloat162float(__float2bfloat16_rn(v.w));
                *(uint2*)&sAhi[row * SSTRIDE + c4] =
                    make_uint2(pack_bf2(hx, hy), pack_bf2(hz, hw));
                *(uint2*)&sAlo[row * SSTRIDE + c4] =
                    make_uint2(pack_bf2(v.x - hx, v.y - hy), pack_bf2(v.z - hz, v.w - hw));
            } else {
                *(uint2*)&sAhi[row * SSTRIDE + c4] =
                    make_uint2(pack_bf2(v.x, v.y), pack_bf2(v.z, v.w));
            }
        }
#pragma unroll
        for (int it = 0; it < 2; it++) {
            int f   = tid + it * 256;
            int row = f >> 3;
            int c4  = (f & 7) * 4;
            float4 v = *(const float4*)(W + (size_t)(bn + row) * DMODEL + k0 + c4);
            if (NT == 3) {
                float hx = __bfloat162float(__float2bfloat16_rn(v.x));
                float hy = __bfloat162float(__float2bfloat16_rn(v.y));
                float hz = __bfloat162float(__float2bfloat16_rn(v.z));
                float hw = __bfloat162float(__float2bfloat16_rn(v.w));
                *(uint2*)&sBhi[row * SSTRIDE + c4] =
                    make_uint2(pack_bf2(hx, hy), pack_bf2(hz, hw));
                *(uint2*)&sBlo[row * SSTRIDE + c4] =
                    make_uint2(pack_bf2(v.x - hx, v.y - hy), pack_bf2(v.z - hz, v.w - hw));
            } else {
                *(uint2*)&sBhi[row * SSTRIDE + c4] =
                    make_uint2(pack_bf2(v.x, v.y), pack_bf2(v.z, v.w));
            }
        }
        __syncthreads();

#pragma unroll
        for (int ks = 0; ks < 32; ks += 16) {
            uint32_t ah[2][4], al[2][4], bh[2][4], bl[2][4];
#pragma unroll
            for (int i = 0; i < 2; i++) {
                uint32_t off = (uint32_t)(i * 16 * (SSTRIDE*2) + ks * 2);
                ldsm_x4(ah[i][0], ah[i][1], ah[i][2], ah[i][3], aHiB + off);
                if (NT == 3)
                    ldsm_x4(al[i][0], al[i][1], al[i][2], al[i][3], aLoB + off);
            }
#pragma unroll
            for (int jt = 0; jt < 2; jt++) {
                uint32_t off = (uint32_t)(jt * 16 * (SSTRIDE*2) + ks * 2);
                ldsm_x4(bh[jt][0], bh[jt][1], bh[jt][2], bh[jt][3], bHiB + off);
                if (NT == 3)
                    ldsm_x4(bl[jt][0], bl[jt][1], bl[jt][2], bl[jt][3], bLoB + off);
            }
#pragma unroll
            for (int i = 0; i < 2; i++)
#pragma unroll
                for (int jt = 0; jt < 2; jt++)
#pragma unroll
                    for (int jj = 0; jj < 2; jj++) {
                        int j = jt * 2 + jj;
                        MMA_BF16(c[i][j], ah[i], &bh[jt][2*jj]);
                        if (NT == 3) {
                            MMA_BF16(c[i][j], ah[i], &bl[jt][2*jj]);
                            MMA_BF16(c[i][j], al[i], &bh[jt][2*jj]);
                        }
                    }
        }
        __syncthreads();
    }

    // Epilogue
#pragma unroll
    for (int j = 0; j < 4; j++) {
        int col = bn + wn * 32 + j * 8 + (lane & 3) * 2;
        float bx = bias[col], by = bias[col + 1];
#pragma unroll
        for (int i = 0; i < 2; i++) {
            int row0 = bm + wm * 32 + i * 16 + (lane >> 2);
            float v0 = c[i][j][0] + bx, v1 = c[i][j][1] + by;
            float v2 = c[i][j][2] + bx, v3 = c[i][j][3] + by;
            if (OM == 0) {
                *(float2*)(C32 + (size_t)row0 * DMODEL + col)       = make_float2(v0, v1);
                *(float2*)(C32 + (size_t)(row0 + 8) * DMODEL + col) = make_float2(v2, v3);
            } else if (OM == 1) {
                *(uint32_t*)(Cb + (size_t)row0 * DMODEL + col)       = pack_bf2(v0*oscale, v1*oscale);
                *(uint32_t*)(Cb + (size_t)(row0 + 8) * DMODEL + col) = pack_bf2(v2*oscale, v3*oscale);
            } else {   // OM == 3: fp16
                *(uint32_t*)(Ch + (size_t)row0 * DMODEL + col)       = pack_h2(v0, v1);
                *(uint32_t*)(Ch + (size_t)(row0 + 8) * DMODEL + col) = pack_h2(v2, v3);
            }
        }
    }
}

// ---------------------------------------------------------------------------
// Flash attention via mma.sync. S = QK^T in bf16 (1 term); P*V in fp16 with
// P hi/lo split (2 terms), V single fp16. K/V prefetched into registers to
// overlap gmem latency with PV compute.
// ---------------------------------------------------------------------------
#define ASTR 72   // 16-bit elems per smem row (64 data + 8 pad) = 144 B

__global__ __launch_bounds__(256, 2)
void attn_mma_kernel(const int* __restrict__ mask)
{
    __shared__ __align__(16) char sraw[2 * 64 * ASTR * 2];   // 18432 B
    __nv_bfloat16* sQ = (__nv_bfloat16*)sraw;                // staging (pre-loop, full)
    __nv_bfloat16* sK = (__nv_bfloat16*)sraw;                // [64 x ASTR]
    __half*        sV = (__half*)(sraw + 64*ASTR*2);         // [64 x ASTR]

    const int tid = threadIdx.x;
    const int w   = tid >> 5;
    const int L   = tid & 31;
    const int qr  = L >> 2;
    const int qc  = L & 3;
    const int q0  = blockIdx.x * 128;
    const int h   = blockIdx.y;
    const int b   = blockIdx.z;

    // ---- Stage Q tile [128 x 64] bf16 (already scaled) ----
    {
        const __nv_bfloat16* Qb = g_Qb + ((size_t)b * NQ + q0) * DMODEL + h * HD;
#pragma unroll
        for (int it = 0; it < 4; it++) {
            int f   = tid + it * 256;
            int row = f >> 3;
            int c8  = (f & 7) * 8;
            *(uint4*)&sQ[row * ASTR + c8] =
                *(const uint4*)(Qb + (size_t)row * DMODEL + c8);
        }
    }
    __syncthreads();

    uint32_t qa[4][4];
    {
        uint32_t base = smem_u32(sQ) + (w * 16 + (L & 15)) * (ASTR*2) + (L >> 4) * 16;
#pragma unroll
        for (int kk = 0; kk < 4; kk++)
            ldsm_x4(qa[kk][0], qa[kk][1], qa[kk][2], qa[kk][3], base + kk * 32);
    }

    float m0 = -INFINITY, m1 = -INFINITY, l0 = 0.f, l1 = 0.f;
    float o[8][4];
#pragma unroll
    for (int j = 0; j < 8; j++)
#pragma unroll
        for (int r = 0; r < 4; r++) o[j][r] = 0.f;

    const int* mrow0 = mask + ((size_t)(b * NQ + q0 + w * 16 + qr)) * NK + 2 * qc;
    const int* mrow1 = mrow0 + (size_t)8 * NK;

    const uint32_t kB = smem_u32(sK) + (L & 7) * (ASTR*2) + (L >> 3) * 16;
    const uint32_t vB = smem_u32(sV) + L * (ASTR*2);

    // per-thread gmem load coords (same for K and V)
    const int ldrow0 = tid >> 3;            // it=0 rows 0..31
    const int ldc8   = (tid & 7) * 8;
    const __nv_bfloat16* Kb = g_Kb + ((size_t)b * NK) * DMODEL + h * HD
                              + (size_t)ldrow0 * DMODEL + ldc8;
    const __half*        Vb = g_Vh + ((size_t)b * NK) * DMODEL + h * HD
                              + (size_t)ldrow0 * DMODEL + ldc8;
    const int sidx0 = ldrow0 * ASTR + ldc8;

    // prologue prefetch (tile 0)
    uint4 pk0 = *(const uint4*)(Kb);
    uint4 pk1 = *(const uint4*)(Kb + (size_t)32 * DMODEL);
    uint4 pv0 = *(const uint4*)(Vb);
    uint4 pv1 = *(const uint4*)(Vb + (size_t)32 * DMODEL);

    for (int kt = 0; kt < NK / 64; kt++) {
        __syncthreads();   // prior tile fully consumed (and Q frags read, first iter)
        *(uint4*)&sK[sidx0]            = pk0;
        *(uint4*)&sK[sidx0 + 32*ASTR]  = pk1;
        *(uint4*)&sV[sidx0]            = pv0;
        *(uint4*)&sV[sidx0 + 32*ASTR]  = pv1;
        __syncthreads();

        // prefetch next tile during compute
        if (kt + 1 < NK / 64) {
            size_t off = (size_t)(kt + 1) * 64 * DMODEL;
            pk0 = *(const uint4*)(Kb + off);
            pk1 = *(const uint4*)(Kb + off + (size_t)32 * DMODEL);
            pv0 = *(const uint4*)(Vb + off);
            pv1 = *(const uint4*)(Vb + off + (size_t)32 * DMODEL);
        }
        const int k0 = kt * 64;

        // ---- S = Q K^T (bf16) ----
        float c[8][4];
#pragma unroll
        for (int j = 0; j < 8; j++) {
            uint32_t kb0[4], kb1[4];
            uint32_t a0 = kB + j * 8 * (ASTR*2);
            ldsm_x4(kb0[0], kb0[1], kb0[2], kb0[3], a0);
            ldsm_x4(kb1[0], kb1[1], kb1[2], kb1[3], a0 + 64);
            c[j][0] = c[j][1] = c[j][2] = c[j][3] = 0.f;
            MMA_BF16(c[j], qa[0], &kb0[0]);
            MMA_BF16(c[j], qa[1], &kb0[2]);
            MMA_BF16(c[j], qa[2], &kb1[0]);
            MMA_BF16(c[j], qa[3], &kb1[2]);
        }

        // ---- online softmax (pre-mask max) ----
        float mx0 = -INFINITY, mx1 = -INFINITY;
#pragma unroll
        for (int j = 0; j < 8; j++) {
            mx0 = fmaxf(mx0, fmaxf(c[j][0], c[j][1]));
            mx1 = fmaxf(mx1, fmaxf(c[j][2], c[j][3]));
        }
        mx0 = fmaxf(mx0, __shfl_xor_sync(0xffffffffu, mx0, 1));
        mx0 = fmaxf(mx0, __shfl_xor_sync(0xffffffffu, mx0, 2));
        mx1 = fmaxf(mx1, __shfl_xor_sync(0xffffffffu, mx1, 1));
        mx1 = fmaxf(mx1, __shfl_xor_sync(0xffffffffu, mx1, 2));
        float nm0 = fmaxf(m0, mx0), nm1 = fmaxf(m1, mx1);
        float f0 = __expf(m0 - nm0), f1 = __expf(m1 - nm1);
        l0 *= f0; l1 *= f1;
#pragma unroll
        for (int j = 0; j < 8; j++) {
            o[j][0] *= f0; o[j][1] *= f0; o[j][2] *= f1; o[j][3] *= f1;
        }
        m0 = nm0; m1 = nm1;

        // ---- P = mask ? exp(S-m) : 0 ; fp16 hi/lo fragments ----
        uint32_t ph[4][4], pl[4][4];
#pragma unroll
        for (int kk = 0; kk < 4; kk++) {
#pragma unroll
            for (int hh = 0; hh < 2; hh++) {
                int j = kk * 2 + hh;
                int2 mv0 = *(const int2*)(mrow0 + k0 + 8 * j);
                int2 mv1 = *(const int2*)(mrow1 + k0 + 8 * j);
                float p0 = mv0.x ? __expf(c[j][0] - m0) : 0.f;
                float p1 = mv0.y ? __expf(c[j][1] - m0) : 0.f;
                float p2 = mv1.x ? __expf(c[j][2] - m1) : 0.f;
                float p3 = mv1.y ? __expf(c[j][3] - m1) : 0.f;
                l0 += p0 + p1; l1 += p2 + p3;
                float h0 = __half2float(__float2half_rn(p0));
                float h1 = __half2float(__float2half_rn(p1));
                float h2 = __half2float(__float2half_rn(p2));
                float h3 = __half2float(__float2half_rn(p3));
                ph[kk][2*hh]   = pack_h2(p0, p1);
                ph[kk][2*hh+1] = pack_h2(p2, p3);
                pl[kk][2*hh]   = pack_h2(p0 - h0, p1 - h1);
                pl[kk][2*hh+1] = pack_h2(p2 - h2, p3 - h3);
            }
        }

        // ---- O += P * V (fp16, 2 terms) ----
#pragma unroll
        for (int j = 0; j < 8; j++) {
            uint32_t v0[4], v1[4];
            ldsm_x4_t(v0[0], v0[1], v0[2], v0[3], vB + j * 16);
            ldsm_x4_t(v1[0], v1[1], v1[2], v1[3], vB + 32 * (ASTR*2) + j * 16);
            MMA_FP16(o[j], ph[0], &v0[0]);
            MMA_FP16(o[j], ph[1], &v0[2]);
            MMA_FP16(o[j], ph[2], &v1[0]);
            MMA_FP16(o[j], ph[3], &v1[2]);
            MMA_FP16(o[j], pl[0], &v0[0]);
            MMA_FP16(o[j], pl[1], &v0[2]);
            MMA_FP16(o[j], pl[2], &v1[0]);
            MMA_FP16(o[j], pl[3], &v1[2]);
        }
    }

    // ---- finalize ----
    l0 += __shfl_xor_sync(0xffffffffu, l0, 1);
    l0 += __shfl_xor_sync(0xffffffffu, l0, 2);
    l1 += __shfl_xor_sync(0xffffffffu, l1, 1);
    l1 += __shfl_xor_sync(0xffffffffu, l1, 2);
    float inv0 = 1.f / (l0 + EPSV);
    float inv1 = 1.f / (l1 + EPSV);

    float* Ob = g_O + ((size_t)b * NQ + q0 + w * 16) * DMODEL + h * HD;
#pragma unroll
    for (int j = 0; j < 8; j++) {
        int col = 8 * j + 2 * qc;
        *(float2*)(Ob + (size_t)qr * DMODEL + col) =
            make_float2(o[j][0] * inv0, o[j][1] * inv0);
        *(float2*)(Ob + (size_t)(qr + 8) * DMODEL + col) =
            make_float2(o[j][2] * inv1, o[j][3] * inv1);
    }
}

// ---------------------------------------------------------------------------
extern "C" void kernel_launch(void* const* d_in, const int* in_sizes, int n_in,
                              void* d_out, int out_size)
{
    const float* Q    = (const float*)d_in[0];
    const float* K    = (const float*)d_in[1];
    const int*   mask = (const int*)  d_in[2];
    const float* Wq   = (const float*)d_in[3];
    const float* bq   = (const float*)d_in[4];
    const float* Wk   = (const float*)d_in[5];
    const float* bk   = (const float*)d_in[6];
    const float* Wv   = (const float*)d_in[7];
    const float* bv   = (const float*)d_in[8];
    const float* Wo   = (const float*)d_in[9];
    const float* bo   = (const float*)d_in[10];
    float* out = (float*)d_out;

    __nv_bfloat16 *pQb, *pKb;
    __half *pVh;
    float *pO;
    cudaGetSymbolAddress((void**)&pQb, g_Qb);
    cudaGetSymbolAddress((void**)&pKb, g_Kb);
    cudaGetSymbolAddress((void**)&pVh, g_Vh);
    cudaGetSymbolAddress((void**)&pO,  g_O);

    dim3 gG(DMODEL / 64, (BATCH * NQ) / 128);  // (16, 32) = 512 CTAs

    gemm_mma<1,1><<<gG, 256>>>(Q, Wq, bq, nullptr, pQb, nullptr, SCALE);  // Q -> bf16 scaled
    gemm_mma<1,1><<<gG, 256>>>(K, Wk, bk, nullptr, pKb, nullptr, 1.0f);   // K -> bf16
    gemm_mma<3,3><<<gG, 256>>>(K, Wv, bv, nullptr, nullptr, pVh, 1.0f);   // V -> fp16

    attn_mma_kernel<<<dim3(NQ / 128, NH, BATCH), 256>>>(mask);

    gemm_mma<3,0><<<gG, 256>>>(pO, Wo, bo, out, nullptr, nullptr, 1.0f);  // O -> fp32
}